// round 2
// baseline (speedup 1.0000x reference)
#include <cuda_runtime.h>
#include <math.h>

#define NNODES 50000
#define NEDGES 1200000
#define NOD    10000
#define DNODE  16
#define DEDGE  8
#define HID    64
#define NLAYERS 3
#define TE     128
#define KMIN   1.0f
#define KMAX   50.0f

// ---------- scratch (device globals; no runtime allocation) ----------
__device__ float g_E [(size_t)NEDGES * HID];
__device__ float g_H0[(size_t)NNODES * HID];
__device__ float g_H1[(size_t)NNODES * HID];
__device__ float g_Hm[(size_t)NNODES * HID];
__device__ float g_AG[(size_t)NNODES * HID];
__device__ float g_GE[HID];

// ---------- packed f32x2 helpers ----------
__device__ __forceinline__ unsigned long long pack2(float x, float y) {
    unsigned long long r; asm("mov.b64 %0,{%1,%2};" : "=l"(r) : "f"(x), "f"(y)); return r;
}
__device__ __forceinline__ unsigned long long dup2(float x) {
    unsigned long long r; asm("mov.b64 %0,{%1,%1};" : "=l"(r) : "f"(x)); return r;
}
__device__ __forceinline__ float2 unpack2(unsigned long long v) {
    float2 f; asm("mov.b64 {%0,%1},%2;" : "=f"(f.x), "=f"(f.y) : "l"(v)); return f;
}
__device__ __forceinline__ void fma2(unsigned long long& a,
                                     unsigned long long x, unsigned long long y) {
    asm("fma.rn.f32x2 %0,%1,%2,%0;" : "+l"(a) : "l"(x), "l"(y));
}

// ---------- h0 = relu(NF @ Wn + bn) ----------
__global__ __launch_bounds__(256) void k_node_proj(
    const float* __restrict__ NF, const float* __restrict__ Wn,
    const float* __restrict__ bn, float* __restrict__ H)
{
    __shared__ float Ws[DNODE * HID];
    __shared__ float xs[16][DNODE];
    int tid = threadIdx.x;
    int rl = tid >> 4, j0 = (tid & 15) * 4;
    long r0 = (long)blockIdx.x * 16;
    ((float4*)Ws)[tid] = ((const float4*)Wn)[tid];
    xs[tid >> 4][tid & 15] = NF[r0 * DNODE + tid];
    __syncthreads();
    float4 b = *(const float4*)(bn + j0);
    unsigned long long a0 = pack2(b.x, b.y), a1 = pack2(b.z, b.w);
    #pragma unroll
    for (int k = 0; k < DNODE; k++) {
        unsigned long long ap = dup2(xs[rl][k]);
        const unsigned long long* w = (const unsigned long long*)(Ws + k * HID + j0);
        fma2(a0, ap, w[0]); fma2(a1, ap, w[1]);
    }
    float2 v0 = unpack2(a0), v1 = unpack2(a1);
    *(float4*)(H + (r0 + rl) * HID + j0) =
        make_float4(fmaxf(v0.x,0.f), fmaxf(v0.y,0.f), fmaxf(v1.x,0.f), fmaxf(v1.y,0.f));
}

// ---------- E = relu(EF @ We + be) ----------
__global__ __launch_bounds__(256) void k_edge_proj(
    const float* __restrict__ EF, const float* __restrict__ We,
    const float* __restrict__ be, float* __restrict__ E)
{
    __shared__ float Ws[DEDGE * HID];
    __shared__ float xs[16][DEDGE];
    int tid = threadIdx.x;
    int rl = tid >> 4, j0 = (tid & 15) * 4;
    long r0 = (long)blockIdx.x * 16;
    if (tid < 128) ((float4*)Ws)[tid] = ((const float4*)We)[tid];
    if (tid < 128) xs[tid >> 3][tid & 7] = EF[r0 * DEDGE + tid];
    __syncthreads();
    float4 b = *(const float4*)(be + j0);
    unsigned long long a0 = pack2(b.x, b.y), a1 = pack2(b.z, b.w);
    #pragma unroll
    for (int k = 0; k < DEDGE; k++) {
        unsigned long long ap = dup2(xs[rl][k]);
        const unsigned long long* w = (const unsigned long long*)(Ws + k * HID + j0);
        fma2(a0, ap, w[0]); fma2(a1, ap, w[1]);
    }
    float2 v0 = unpack2(a0), v1 = unpack2(a1);
    *(float4*)(E + (r0 + rl) * HID + j0) =
        make_float4(fmaxf(v0.x,0.f), fmaxf(v0.y,0.f), fmaxf(v1.x,0.f), fmaxf(v1.y,0.f));
}

// ---------- Hm = h @ Wm_top + bm (no relu); AGG = 0 ----------
__global__ __launch_bounds__(256) void k_hm(
    const float* __restrict__ H, const float* __restrict__ Wtop,
    const float* __restrict__ bm, float* __restrict__ Hm, float* __restrict__ AGG)
{
    __shared__ float Ws[HID * HID];
    __shared__ float xs[16][HID];
    int tid = threadIdx.x;
    int rl = tid >> 4, j0 = (tid & 15) * 4;
    long r0 = (long)blockIdx.x * 16;
    #pragma unroll
    for (int i = 0; i < 4; i++)
        ((float4*)Ws)[tid + i * 256] = ((const float4*)Wtop)[tid + i * 256];
    ((float4*)xs)[tid] = ((const float4*)(H + r0 * HID))[tid];
    __syncthreads();
    float4 b = *(const float4*)(bm + j0);
    unsigned long long a0 = pack2(b.x, b.y), a1 = pack2(b.z, b.w);
    #pragma unroll 8
    for (int k = 0; k < HID; k++) {
        unsigned long long ap = dup2(xs[rl][k]);
        const unsigned long long* w = (const unsigned long long*)(Ws + k * HID + j0);
        fma2(a0, ap, w[0]); fma2(a1, ap, w[1]);
    }
    float2 v0 = unpack2(a0), v1 = unpack2(a1);
    long o = (r0 + rl) * HID + j0;
    *(float4*)(Hm + o)  = make_float4(v0.x, v0.y, v1.x, v1.y);
    *(float4*)(AGG + o) = make_float4(0.f, 0.f, 0.f, 0.f);
}

// ---------- per-edge: m = relu(Hm[src] + E@Wbot); AGG[dst] += m ----------
__global__ __launch_bounds__(128, 4) void k_edge_mp(
    const float* __restrict__ E, const int* __restrict__ src, const int* __restrict__ dst,
    const float* __restrict__ Hm, const float* __restrict__ Wbot, float* __restrict__ AGG)
{
    __shared__ float Es[HID * TE];   // 32KB, transposed edge tile
    __shared__ float Ws[HID * HID];  // 16KB
    int tid = threadIdx.x;
    long e0g = (long)blockIdx.x * TE;

    #pragma unroll
    for (int i = 0; i < 8; i++)
        ((float4*)Ws)[tid + i * 128] = ((const float4*)Wbot)[tid + i * 128];
    {
        const float4* Er = (const float4*)(E + (e0g + tid) * HID);
        #pragma unroll
        for (int kk = 0; kk < 16; kk++) {
            float4 v = Er[kk];
            Es[(4*kk+0)*TE + tid] = v.x;
            Es[(4*kk+1)*TE + tid] = v.y;
            Es[(4*kk+2)*TE + tid] = v.z;
            Es[(4*kk+3)*TE + tid] = v.w;
        }
    }
    __syncthreads();

    int jt = tid & 7, et = tid >> 3;
    int j0 = jt * 8, e0 = et * 8;
    unsigned long long acc[8][4];
    #pragma unroll
    for (int e = 0; e < 8; e++) { acc[e][0]=0; acc[e][1]=0; acc[e][2]=0; acc[e][3]=0; }

    #pragma unroll 4
    for (int k = 0; k < HID; k++) {
        const unsigned long long* w = (const unsigned long long*)(Ws + k * HID + j0);
        unsigned long long w0 = w[0], w1 = w[1], w2 = w[2], w3 = w[3];
        const float* ar = Es + k * TE + e0;
        float4 aA = *(const float4*)ar;
        float4 aB = *(const float4*)(ar + 4);
        float av[8] = {aA.x, aA.y, aA.z, aA.w, aB.x, aB.y, aB.z, aB.w};
        #pragma unroll
        for (int e = 0; e < 8; e++) {
            unsigned long long ap = dup2(av[e]);
            fma2(acc[e][0], ap, w0);
            fma2(acc[e][1], ap, w1);
            fma2(acc[e][2], ap, w2);
            fma2(acc[e][3], ap, w3);
        }
    }

    #pragma unroll
    for (int e = 0; e < 8; e++) {
        long eg = e0g + e0 + e;
        int s = src[eg], d = dst[eg];
        const float* hm = Hm + (long)s * HID + j0;
        float4 h0 = *(const float4*)hm;
        float4 h1 = *(const float4*)(hm + 4);
        float2 m0 = unpack2(acc[e][0]), m1 = unpack2(acc[e][1]);
        float2 m2 = unpack2(acc[e][2]), m3 = unpack2(acc[e][3]);
        float v0 = fmaxf(m0.x + h0.x, 0.f), v1 = fmaxf(m0.y + h0.y, 0.f);
        float v2 = fmaxf(m1.x + h0.z, 0.f), v3 = fmaxf(m1.y + h0.w, 0.f);
        float v4 = fmaxf(m2.x + h1.x, 0.f), v5 = fmaxf(m2.y + h1.y, 0.f);
        float v6 = fmaxf(m3.x + h1.z, 0.f), v7 = fmaxf(m3.y + h1.w, 0.f);
        float* ag = AGG + (long)d * HID + j0;
        asm volatile("red.global.add.v4.f32 [%0], {%1,%2,%3,%4};"
                     :: "l"(ag),     "f"(v0), "f"(v1), "f"(v2), "f"(v3) : "memory");
        asm volatile("red.global.add.v4.f32 [%0], {%1,%2,%3,%4};"
                     :: "l"(ag + 4), "f"(v4), "f"(v5), "f"(v6), "f"(v7) : "memory");
    }
}

// ---------- h' = relu([h, agg] @ Wu + bu) + h ----------
__global__ __launch_bounds__(256) void k_update(
    const float* __restrict__ Hin, const float* __restrict__ AGG,
    const float* __restrict__ Wu, const float* __restrict__ bu, float* __restrict__ Hout)
{
    __shared__ float Ws[2 * HID * HID];  // 32KB
    __shared__ float xs[16][HID];
    __shared__ float as_[16][HID];
    int tid = threadIdx.x;
    int rl = tid >> 4, j0 = (tid & 15) * 4;
    long r0 = (long)blockIdx.x * 16;
    #pragma unroll
    for (int i = 0; i < 8; i++)
        ((float4*)Ws)[tid + i * 256] = ((const float4*)Wu)[tid + i * 256];
    ((float4*)xs)[tid]  = ((const float4*)(Hin + r0 * HID))[tid];
    ((float4*)as_)[tid] = ((const float4*)(AGG + r0 * HID))[tid];
    __syncthreads();
    float4 b = *(const float4*)(bu + j0);
    unsigned long long a0 = pack2(b.x, b.y), a1 = pack2(b.z, b.w);
    #pragma unroll 8
    for (int k = 0; k < HID; k++) {
        unsigned long long ap = dup2(xs[rl][k]);
        const unsigned long long* w = (const unsigned long long*)(Ws + k * HID + j0);
        fma2(a0, ap, w[0]); fma2(a1, ap, w[1]);
    }
    #pragma unroll 8
    for (int k = 0; k < HID; k++) {
        unsigned long long ap = dup2(as_[rl][k]);
        const unsigned long long* w = (const unsigned long long*)(Ws + (HID + k) * HID + j0);
        fma2(a0, ap, w[0]); fma2(a1, ap, w[1]);
    }
    float2 v0 = unpack2(a0), v1 = unpack2(a1);
    long o = (r0 + rl) * HID + j0;
    *(float4*)(Hout + o) = make_float4(
        fmaxf(v0.x,0.f) + xs[rl][j0+0], fmaxf(v0.y,0.f) + xs[rl][j0+1],
        fmaxf(v1.x,0.f) + xs[rl][j0+2], fmaxf(v1.y,0.f) + xs[rl][j0+3]);
}

// ---------- A = h @ Ws1_top ; B = h @ Ws1_bot (no bias/relu here) ----------
__global__ __launch_bounds__(256) void k_ab(
    const float* __restrict__ H, const float* __restrict__ Ws1,
    float* __restrict__ A, float* __restrict__ B)
{
    __shared__ float Ws[2 * HID * HID];
    __shared__ float xs[16][HID];
    int tid = threadIdx.x;
    int rl = tid >> 4, j0 = (tid & 15) * 4;
    long r0 = (long)blockIdx.x * 16;
    #pragma unroll
    for (int i = 0; i < 8; i++)
        ((float4*)Ws)[tid + i * 256] = ((const float4*)Ws1)[tid + i * 256];
    ((float4*)xs)[tid] = ((const float4*)(H + r0 * HID))[tid];
    __syncthreads();
    unsigned long long a0 = 0, a1 = 0, b0 = 0, b1 = 0;
    #pragma unroll 8
    for (int k = 0; k < HID; k++) {
        unsigned long long ap = dup2(xs[rl][k]);
        const unsigned long long* wt = (const unsigned long long*)(Ws + k * HID + j0);
        const unsigned long long* wb = (const unsigned long long*)(Ws + (HID + k) * HID + j0);
        fma2(a0, ap, wt[0]); fma2(a1, ap, wt[1]);
        fma2(b0, ap, wb[0]); fma2(b1, ap, wb[1]);
    }
    float2 x0 = unpack2(a0), x1 = unpack2(a1), y0 = unpack2(b0), y1 = unpack2(b1);
    long o = (r0 + rl) * HID + j0;
    *(float4*)(A + o) = make_float4(x0.x, x0.y, x1.x, x1.y);
    *(float4*)(B + o) = make_float4(y0.x, y0.y, y1.x, y1.y);
}

// ---------- per-OD scores ----------
__global__ __launch_bounds__(256) void k_scores(
    const float* __restrict__ A, const float* __restrict__ B,
    const int* __restrict__ ods, const int* __restrict__ odd,
    const float* __restrict__ bs1, const float* __restrict__ Ws2,
    const float* __restrict__ bs2, float* __restrict__ out)
{
    int warp = threadIdx.x >> 5, lane = threadIdx.x & 31;
    int p = blockIdx.x * 8 + warp;
    int s = ods[p], d = odd[p];
    const float* Ar = A + (long)s * HID;
    const float* Br = B + (long)d * HID;
    int j1 = lane, j2 = lane + 32;
    float t1 = fmaxf(Ar[j1] + Br[j1] + bs1[j1], 0.f);
    float t2 = fmaxf(Ar[j2] + Br[j2] + bs1[j2], 0.f);
    float v = t1 * Ws2[j1] + t2 * Ws2[j2];
    #pragma unroll
    for (int o = 16; o > 0; o >>= 1) v += __shfl_down_sync(0xffffffffu, v, o);
    if (lane == 0) out[p] = v + bs2[0];
}

// ---------- graph embed sum ----------
__global__ void k_zero_ge() { g_GE[threadIdx.x] = 0.f; }

__global__ __launch_bounds__(256) void k_gesum(const float* __restrict__ H)
{
    __shared__ float part[4][HID];
    int tid = threadIdx.x;
    int j = tid & 63, g = tid >> 6;
    long base = (long)blockIdx.x * 256 + g;
    float acc = 0.f;
    #pragma unroll 4
    for (int i = 0; i < 64; i++) {
        long r = base + (long)i * 4;
        if (r < NNODES) acc += H[r * HID + j];
    }
    part[g][j] = acc;
    __syncthreads();
    if (g == 0) {
        float s = part[0][j] + part[1][j] + part[2][j] + part[3][j];
        atomicAdd(&g_GE[j], s);
    }
}

// ---------- dynamic-K head (single warp) ----------
__global__ void k_khead(
    const float* __restrict__ TS,
    const float* __restrict__ Wk1, const float* __restrict__ bk1,
    const float* __restrict__ Wk2, const float* __restrict__ bk2,
    const float* __restrict__ Wk3, const float* __restrict__ bk3,
    float* __restrict__ out)
{
    __shared__ float x[68];
    __shared__ float h1[32];
    __shared__ float h2[16];
    int lane = threadIdx.x;
    x[lane]      = g_GE[lane] * (1.0f / NNODES);
    x[lane + 32] = g_GE[lane + 32] * (1.0f / NNODES);
    if (lane < 4) x[64 + lane] = TS[lane];
    __syncwarp();
    float a = bk1[lane];
    #pragma unroll 4
    for (int k = 0; k < 68; k++) a += x[k] * Wk1[k * 32 + lane];
    h1[lane] = fmaxf(a, 0.f);
    __syncwarp();
    if (lane < 16) {
        float b = bk2[lane];
        #pragma unroll
        for (int k = 0; k < 32; k++) b += h1[k] * Wk2[k * 16 + lane];
        h2[lane] = fmaxf(b, 0.f);
    }
    __syncwarp();
    if (lane == 0) {
        float raw = bk3[0];
        #pragma unroll
        for (int k = 0; k < 16; k++) raw += h2[k] * Wk3[k];
        float sig = 1.0f / (1.0f + expf(-raw));
        out[NOD] = KMIN + sig * (KMAX - KMIN);
    }
}

// ---------- launcher ----------
extern "C" void kernel_launch(void* const* d_in, const int* in_sizes, int n_in,
                              void* d_out, int out_size)
{
    const float* NF  = (const float*)d_in[0];
    const int*   EI  = (const int*)  d_in[1];
    const float* EF  = (const float*)d_in[2];
    const int*   OD  = (const int*)  d_in[3];
    const float* TS  = (const float*)d_in[4];
    const float* Wn  = (const float*)d_in[5];
    const float* bn  = (const float*)d_in[6];
    const float* We  = (const float*)d_in[7];
    const float* be  = (const float*)d_in[8];
    const float* Wm  = (const float*)d_in[9];
    const float* bm  = (const float*)d_in[10];
    const float* Wu  = (const float*)d_in[11];
    const float* bu  = (const float*)d_in[12];
    const float* Ws1 = (const float*)d_in[13];
    const float* bs1 = (const float*)d_in[14];
    const float* Ws2 = (const float*)d_in[15];
    const float* bs2 = (const float*)d_in[16];
    const float* Wk1 = (const float*)d_in[17];
    const float* bk1 = (const float*)d_in[18];
    const float* Wk2 = (const float*)d_in[19];
    const float* bk2 = (const float*)d_in[20];
    const float* Wk3 = (const float*)d_in[21];
    const float* bk3 = (const float*)d_in[22];
    float* out = (float*)d_out;

    float *E, *H0, *H1, *Hm, *AG;
    cudaGetSymbolAddress((void**)&E,  g_E);
    cudaGetSymbolAddress((void**)&H0, g_H0);
    cudaGetSymbolAddress((void**)&H1, g_H1);
    cudaGetSymbolAddress((void**)&Hm, g_Hm);
    cudaGetSymbolAddress((void**)&AG, g_AG);

    const int* src = EI;
    const int* dst = EI + NEDGES;
    const int* ods = OD;
    const int* odd = OD + NOD;

    k_node_proj<<<NNODES / 16, 256>>>(NF, Wn, bn, H0);
    k_edge_proj<<<NEDGES / 16, 256>>>(EF, We, be, E);

    float* Hcur = H0;
    float* Hnext = H1;
    for (int l = 0; l < NLAYERS; l++) {
        const float* Wml = Wm + (size_t)l * 2 * HID * HID;
        const float* bml = bm + (size_t)l * HID;
        const float* Wul = Wu + (size_t)l * 2 * HID * HID;
        const float* bul = bu + (size_t)l * HID;
        k_hm<<<NNODES / 16, 256>>>(Hcur, Wml, bml, Hm, AG);
        k_edge_mp<<<NEDGES / TE, 128>>>(E, src, dst, Hm, Wml + HID * HID, AG);
        k_update<<<NNODES / 16, 256>>>(Hcur, AG, Wul, bul, Hnext);
        float* t = Hcur; Hcur = Hnext; Hnext = t;
    }

    // scores: reuse Hm as A, AG as B
    k_ab<<<NNODES / 16, 256>>>(Hcur, Ws1, Hm, AG);
    k_scores<<<NOD / 8, 256>>>(Hm, AG, ods, odd, bs1, Ws2, bs2, out);

    k_zero_ge<<<1, HID>>>();
    k_gesum<<<(NNODES + 255) / 256, 256>>>(Hcur);
    k_khead<<<1, 32>>>(TS, Wk1, bk1, Wk2, bk2, Wk3, bk3, out);
}

// round 3
// speedup vs baseline: 1.5404x; 1.5404x over previous
#include <cuda_runtime.h>
#include <cuda_bf16.h>
#include <math.h>

#define NNODES 50000
#define NEDGES 1200000
#define NOD    10000
#define DNODE  16
#define DEDGE  8
#define HID    64
#define NLAYERS 3
#define TE     128
#define NROWS  32
#define KMIN   1.0f
#define KMAX   50.0f

// ---------- scratch (device globals; no runtime allocation) ----------
__device__ __nv_bfloat16 g_Ebf[(size_t)NEDGES * HID];   // tiled [tile][HID][TE]
__device__ float g_H0[(size_t)NNODES * HID];
__device__ float g_H1[(size_t)NNODES * HID];
__device__ float g_Hm[(size_t)NNODES * HID];
__device__ float g_AG[(size_t)NNODES * HID];
__device__ float g_GE[HID];

// ---------- packed f32x2 helpers ----------
__device__ __forceinline__ unsigned long long pack2(float x, float y) {
    unsigned long long r; asm("mov.b64 %0,{%1,%2};" : "=l"(r) : "f"(x), "f"(y)); return r;
}
__device__ __forceinline__ unsigned long long dup2(float x) {
    unsigned long long r; asm("mov.b64 %0,{%1,%1};" : "=l"(r) : "f"(x)); return r;
}
__device__ __forceinline__ float2 unpack2(unsigned long long v) {
    float2 f; asm("mov.b64 {%0,%1},%2;" : "=f"(f.x), "=f"(f.y) : "l"(v)); return f;
}
__device__ __forceinline__ void fma2(unsigned long long& a,
                                     unsigned long long x, unsigned long long y) {
    asm("fma.rn.f32x2 %0,%1,%2,%0;" : "+l"(a) : "l"(x), "l"(y));
}

// ---------- h0 = relu(NF @ Wn + bn) ----------
__global__ __launch_bounds__(256) void k_node_proj(
    const float* __restrict__ NF, const float* __restrict__ Wn,
    const float* __restrict__ bn, float* __restrict__ H)
{
    __shared__ float Ws[DNODE * HID];
    __shared__ float xs[16][DNODE];
    int tid = threadIdx.x;
    int rl = tid >> 4, j0 = (tid & 15) * 4;
    long r0 = (long)blockIdx.x * 16;
    ((float4*)Ws)[tid] = ((const float4*)Wn)[tid];
    xs[tid >> 4][tid & 15] = NF[r0 * DNODE + tid];
    __syncthreads();
    float4 b = *(const float4*)(bn + j0);
    unsigned long long a0 = pack2(b.x, b.y), a1 = pack2(b.z, b.w);
    #pragma unroll
    for (int k = 0; k < DNODE; k++) {
        unsigned long long ap = dup2(xs[rl][k]);
        const unsigned long long* w = (const unsigned long long*)(Ws + k * HID + j0);
        fma2(a0, ap, w[0]); fma2(a1, ap, w[1]);
    }
    float2 v0 = unpack2(a0), v1 = unpack2(a1);
    *(float4*)(H + (r0 + rl) * HID + j0) =
        make_float4(fmaxf(v0.x,0.f), fmaxf(v0.y,0.f), fmaxf(v1.x,0.f), fmaxf(v1.y,0.f));
}

// ---------- E tile = relu(EF @ We + be), bf16, pre-transposed [HID][TE] ----------
__global__ __launch_bounds__(256) void k_edge_proj(
    const float* __restrict__ EF, const float* __restrict__ We,
    const float* __restrict__ be, __nv_bfloat16* __restrict__ E)
{
    __shared__ float Ws[DEDGE * HID];                       // 2KB
    __shared__ float efs[TE * DEDGE];                       // 4KB
    __shared__ __align__(16) __nv_bfloat16 Es[HID * TE];    // 16KB
    int tid = threadIdx.x;
    long e0g = (long)blockIdx.x * TE;
    if (tid < 128) ((float4*)Ws)[tid] = ((const float4*)We)[tid];
    ((float4*)efs)[tid] = ((const float4*)(EF + e0g * DEDGE))[tid];  // 1024 floats
    __syncthreads();
    int jt = tid & 15, et = tid >> 4;
    int j0 = jt * 4;
    float4 b = *(const float4*)(be + j0);
    #pragma unroll
    for (int ee = 0; ee < 8; ee++) {
        int e = et * 8 + ee;
        unsigned long long a0 = pack2(b.x, b.y), a1 = pack2(b.z, b.w);
        const float* x = efs + e * DEDGE;
        #pragma unroll
        for (int k = 0; k < DEDGE; k++) {
            unsigned long long ap = dup2(x[k]);
            const unsigned long long* w = (const unsigned long long*)(Ws + k * HID + j0);
            fma2(a0, ap, w[0]); fma2(a1, ap, w[1]);
        }
        float2 v0 = unpack2(a0), v1 = unpack2(a1);
        Es[(j0+0)*TE + e] = __float2bfloat16(fmaxf(v0.x, 0.f));
        Es[(j0+1)*TE + e] = __float2bfloat16(fmaxf(v0.y, 0.f));
        Es[(j0+2)*TE + e] = __float2bfloat16(fmaxf(v1.x, 0.f));
        Es[(j0+3)*TE + e] = __float2bfloat16(fmaxf(v1.y, 0.f));
    }
    __syncthreads();
    uint4* dst4 = (uint4*)(E + (size_t)blockIdx.x * HID * TE);
    const uint4* src4 = (const uint4*)Es;
    #pragma unroll
    for (int i = 0; i < 4; i++) dst4[tid + i * 256] = src4[tid + i * 256];
}

// ---------- Hm = h @ Wm_top + bm (no relu); AGG = 0 ----------
// 128 threads, 32 rows/block, thread tile = 4 rows x 4 cols
__global__ __launch_bounds__(128) void k_hm(
    const float* __restrict__ H, const float* __restrict__ Wtop,
    const float* __restrict__ bm, float* __restrict__ Hm, float* __restrict__ AGG)
{
    __shared__ float Ws[HID * HID];    // 16KB
    __shared__ float xs[NROWS * HID];  // 8KB
    int tid = threadIdx.x;
    long r0 = (long)blockIdx.x * NROWS;
    int nrow = NNODES - (int)r0; if (nrow > NROWS) nrow = NROWS;
    #pragma unroll
    for (int i = 0; i < 8; i++)
        ((float4*)Ws)[tid + i * 128] = ((const float4*)Wtop)[tid + i * 128];
    #pragma unroll
    for (int i = 0; i < 4; i++) {
        int idx = tid + i * 128;
        if ((idx >> 4) < nrow) ((float4*)xs)[idx] = ((const float4*)(H + r0 * HID))[idx];
    }
    __syncthreads();
    int jt = tid & 15, rt = tid >> 4;
    int j0 = jt * 4, rb = rt * 4;
    float4 b = *(const float4*)(bm + j0);
    unsigned long long acc[4][2];
    #pragma unroll
    for (int i = 0; i < 4; i++) { acc[i][0] = pack2(b.x, b.y); acc[i][1] = pack2(b.z, b.w); }
    #pragma unroll 4
    for (int k = 0; k < HID; k++) {
        const unsigned long long* w = (const unsigned long long*)(Ws + k * HID + j0);
        unsigned long long w0 = w[0], w1 = w[1];
        #pragma unroll
        for (int i = 0; i < 4; i++) {
            unsigned long long ap = dup2(xs[(rb + i) * HID + k]);
            fma2(acc[i][0], ap, w0); fma2(acc[i][1], ap, w1);
        }
    }
    #pragma unroll
    for (int i = 0; i < 4; i++) {
        if (rb + i < nrow) {
            float2 v0 = unpack2(acc[i][0]), v1 = unpack2(acc[i][1]);
            long o = (r0 + rb + i) * HID + j0;
            *(float4*)(Hm + o)  = make_float4(v0.x, v0.y, v1.x, v1.y);
            *(float4*)(AGG + o) = make_float4(0.f, 0.f, 0.f, 0.f);
        }
    }
}

// ---------- per-edge: m = relu(Hm[src] + E@Wbot); AGG[dst] += m ----------
__global__ __launch_bounds__(128, 4) void k_edge_mp(
    const __nv_bfloat16* __restrict__ E, const int* __restrict__ src, const int* __restrict__ dst,
    const float* __restrict__ Hm, const float* __restrict__ Wbot, float* __restrict__ AGG)
{
    __shared__ float Ws[HID * HID];                       // 16KB
    __shared__ __align__(16) __nv_bfloat16 Es[HID * TE];  // 16KB
    int tid = threadIdx.x;
    long e0g = (long)blockIdx.x * TE;

    #pragma unroll
    for (int i = 0; i < 8; i++)
        ((float4*)Ws)[tid + i * 128] = ((const float4*)Wbot)[tid + i * 128];
    const uint4* Eg = (const uint4*)(E + (size_t)blockIdx.x * HID * TE);
    #pragma unroll
    for (int i = 0; i < 8; i++)
        ((uint4*)Es)[tid + i * 128] = Eg[tid + i * 128];
    __syncthreads();

    int jt = tid & 7, et = tid >> 3;
    int j0 = jt * 8, e0 = et * 8;
    unsigned long long acc[8][4];
    #pragma unroll
    for (int e = 0; e < 8; e++) { acc[e][0]=0; acc[e][1]=0; acc[e][2]=0; acc[e][3]=0; }

    #pragma unroll 4
    for (int k = 0; k < HID; k++) {
        const unsigned long long* w = (const unsigned long long*)(Ws + k * HID + j0);
        unsigned long long w0 = w[0], w1 = w[1], w2 = w[2], w3 = w[3];
        uint4 araw = *(const uint4*)(Es + (size_t)k * TE + e0);
        const __nv_bfloat162* bp = (const __nv_bfloat162*)&araw;
        float2 f0 = __bfloat1622float2(bp[0]);
        float2 f1 = __bfloat1622float2(bp[1]);
        float2 f2 = __bfloat1622float2(bp[2]);
        float2 f3 = __bfloat1622float2(bp[3]);
        float av[8] = {f0.x, f0.y, f1.x, f1.y, f2.x, f2.y, f3.x, f3.y};
        #pragma unroll
        for (int e = 0; e < 8; e++) {
            unsigned long long ap = dup2(av[e]);
            fma2(acc[e][0], ap, w0);
            fma2(acc[e][1], ap, w1);
            fma2(acc[e][2], ap, w2);
            fma2(acc[e][3], ap, w3);
        }
    }

    #pragma unroll
    for (int e = 0; e < 8; e++) {
        long eg = e0g + e0 + e;
        int s = src[eg], d = dst[eg];
        const float* hm = Hm + (long)s * HID + j0;
        float4 h0 = *(const float4*)hm;
        float4 h1 = *(const float4*)(hm + 4);
        float2 m0 = unpack2(acc[e][0]), m1 = unpack2(acc[e][1]);
        float2 m2 = unpack2(acc[e][2]), m3 = unpack2(acc[e][3]);
        float v0 = fmaxf(m0.x + h0.x, 0.f), v1 = fmaxf(m0.y + h0.y, 0.f);
        float v2 = fmaxf(m1.x + h0.z, 0.f), v3 = fmaxf(m1.y + h0.w, 0.f);
        float v4 = fmaxf(m2.x + h1.x, 0.f), v5 = fmaxf(m2.y + h1.y, 0.f);
        float v6 = fmaxf(m3.x + h1.z, 0.f), v7 = fmaxf(m3.y + h1.w, 0.f);
        float* ag = AGG + (long)d * HID + j0;
        asm volatile("red.global.add.v4.f32 [%0], {%1,%2,%3,%4};"
                     :: "l"(ag),     "f"(v0), "f"(v1), "f"(v2), "f"(v3) : "memory");
        asm volatile("red.global.add.v4.f32 [%0], {%1,%2,%3,%4};"
                     :: "l"(ag + 4), "f"(v4), "f"(v5), "f"(v6), "f"(v7) : "memory");
    }
}

// ---------- h' = relu([h, agg] @ Wu + bu) + h ----------
// 128 threads, 32 rows/block, thread tile = 4 rows x 4 cols
__global__ __launch_bounds__(128) void k_update(
    const float* __restrict__ Hin, const float* __restrict__ AGG,
    const float* __restrict__ Wu, const float* __restrict__ bu, float* __restrict__ Hout)
{
    __shared__ float Ws[2 * HID * HID];  // 32KB
    __shared__ float xs[NROWS * HID];    // 8KB
    __shared__ float as_[NROWS * HID];   // 8KB
    int tid = threadIdx.x;
    long r0 = (long)blockIdx.x * NROWS;
    int nrow = NNODES - (int)r0; if (nrow > NROWS) nrow = NROWS;
    #pragma unroll
    for (int i = 0; i < 16; i++)
        ((float4*)Ws)[tid + i * 128] = ((const float4*)Wu)[tid + i * 128];
    #pragma unroll
    for (int i = 0; i < 4; i++) {
        int idx = tid + i * 128;
        if ((idx >> 4) < nrow) {
            ((float4*)xs)[idx]  = ((const float4*)(Hin + r0 * HID))[idx];
            ((float4*)as_)[idx] = ((const float4*)(AGG + r0 * HID))[idx];
        }
    }
    __syncthreads();
    int jt = tid & 15, rt = tid >> 4;
    int j0 = jt * 4, rb = rt * 4;
    float4 b = *(const float4*)(bu + j0);
    unsigned long long acc[4][2];
    #pragma unroll
    for (int i = 0; i < 4; i++) { acc[i][0] = pack2(b.x, b.y); acc[i][1] = pack2(b.z, b.w); }
    #pragma unroll 4
    for (int k = 0; k < HID; k++) {
        const unsigned long long* w = (const unsigned long long*)(Ws + k * HID + j0);
        unsigned long long w0 = w[0], w1 = w[1];
        #pragma unroll
        for (int i = 0; i < 4; i++) {
            unsigned long long ap = dup2(xs[(rb + i) * HID + k]);
            fma2(acc[i][0], ap, w0); fma2(acc[i][1], ap, w1);
        }
    }
    #pragma unroll 4
    for (int k = 0; k < HID; k++) {
        const unsigned long long* w = (const unsigned long long*)(Ws + (HID + k) * HID + j0);
        unsigned long long w0 = w[0], w1 = w[1];
        #pragma unroll
        for (int i = 0; i < 4; i++) {
            unsigned long long ap = dup2(as_[(rb + i) * HID + k]);
            fma2(acc[i][0], ap, w0); fma2(acc[i][1], ap, w1);
        }
    }
    #pragma unroll
    for (int i = 0; i < 4; i++) {
        if (rb + i < nrow) {
            float2 v0 = unpack2(acc[i][0]), v1 = unpack2(acc[i][1]);
            const float* xr = xs + (rb + i) * HID + j0;
            long o = (r0 + rb + i) * HID + j0;
            *(float4*)(Hout + o) = make_float4(
                fmaxf(v0.x,0.f) + xr[0], fmaxf(v0.y,0.f) + xr[1],
                fmaxf(v1.x,0.f) + xr[2], fmaxf(v1.y,0.f) + xr[3]);
        }
    }
}

// ---------- A = h @ Ws1_top ; B = h @ Ws1_bot ----------
__global__ __launch_bounds__(128) void k_ab(
    const float* __restrict__ H, const float* __restrict__ Ws1,
    float* __restrict__ A, float* __restrict__ B)
{
    __shared__ float Ws[2 * HID * HID];  // 32KB
    __shared__ float xs[NROWS * HID];    // 8KB
    int tid = threadIdx.x;
    long r0 = (long)blockIdx.x * NROWS;
    int nrow = NNODES - (int)r0; if (nrow > NROWS) nrow = NROWS;
    #pragma unroll
    for (int i = 0; i < 16; i++)
        ((float4*)Ws)[tid + i * 128] = ((const float4*)Ws1)[tid + i * 128];
    #pragma unroll
    for (int i = 0; i < 4; i++) {
        int idx = tid + i * 128;
        if ((idx >> 4) < nrow) ((float4*)xs)[idx] = ((const float4*)(H + r0 * HID))[idx];
    }
    __syncthreads();
    int jt = tid & 15, rt = tid >> 4;
    int j0 = jt * 4, rb = rt * 4;
    unsigned long long aA[4][2], aB[4][2];
    #pragma unroll
    for (int i = 0; i < 4; i++) { aA[i][0]=0; aA[i][1]=0; aB[i][0]=0; aB[i][1]=0; }
    #pragma unroll 4
    for (int k = 0; k < HID; k++) {
        const unsigned long long* wt = (const unsigned long long*)(Ws + k * HID + j0);
        const unsigned long long* wb = (const unsigned long long*)(Ws + (HID + k) * HID + j0);
        unsigned long long t0 = wt[0], t1 = wt[1], b0 = wb[0], b1 = wb[1];
        #pragma unroll
        for (int i = 0; i < 4; i++) {
            unsigned long long ap = dup2(xs[(rb + i) * HID + k]);
            fma2(aA[i][0], ap, t0); fma2(aA[i][1], ap, t1);
            fma2(aB[i][0], ap, b0); fma2(aB[i][1], ap, b1);
        }
    }
    #pragma unroll
    for (int i = 0; i < 4; i++) {
        if (rb + i < nrow) {
            float2 x0 = unpack2(aA[i][0]), x1 = unpack2(aA[i][1]);
            float2 y0 = unpack2(aB[i][0]), y1 = unpack2(aB[i][1]);
            long o = (r0 + rb + i) * HID + j0;
            *(float4*)(A + o) = make_float4(x0.x, x0.y, x1.x, x1.y);
            *(float4*)(B + o) = make_float4(y0.x, y0.y, y1.x, y1.y);
        }
    }
}

// ---------- per-OD scores (also zeroes g_GE from block 0) ----------
__global__ __launch_bounds__(256) void k_scores(
    const float* __restrict__ A, const float* __restrict__ B,
    const int* __restrict__ ods, const int* __restrict__ odd,
    const float* __restrict__ bs1, const float* __restrict__ Ws2,
    const float* __restrict__ bs2, float* __restrict__ out)
{
    if (blockIdx.x == 0 && threadIdx.x < HID) g_GE[threadIdx.x] = 0.f;
    int warp = threadIdx.x >> 5, lane = threadIdx.x & 31;
    int p = blockIdx.x * 8 + warp;
    int s = ods[p], d = odd[p];
    const float* Ar = A + (long)s * HID;
    const float* Br = B + (long)d * HID;
    int j1 = lane, j2 = lane + 32;
    float t1 = fmaxf(Ar[j1] + Br[j1] + bs1[j1], 0.f);
    float t2 = fmaxf(Ar[j2] + Br[j2] + bs1[j2], 0.f);
    float v = t1 * Ws2[j1] + t2 * Ws2[j2];
    #pragma unroll
    for (int o = 16; o > 0; o >>= 1) v += __shfl_down_sync(0xffffffffu, v, o);
    if (lane == 0) out[p] = v + bs2[0];
}

// ---------- graph embed sum ----------
__global__ __launch_bounds__(256) void k_gesum(const float* __restrict__ H)
{
    __shared__ float part[4][HID];
    int tid = threadIdx.x;
    int j = tid & 63, g = tid >> 6;
    long base = (long)blockIdx.x * 256 + g;
    float acc = 0.f;
    #pragma unroll 4
    for (int i = 0; i < 64; i++) {
        long r = base + (long)i * 4;
        if (r < NNODES) acc += H[r * HID + j];
    }
    part[g][j] = acc;
    __syncthreads();
    if (g == 0) {
        float s = part[0][j] + part[1][j] + part[2][j] + part[3][j];
        atomicAdd(&g_GE[j], s);
    }
}

// ---------- dynamic-K head (single warp) ----------
__global__ void k_khead(
    const float* __restrict__ TS,
    const float* __restrict__ Wk1, const float* __restrict__ bk1,
    const float* __restrict__ Wk2, const float* __restrict__ bk2,
    const float* __restrict__ Wk3, const float* __restrict__ bk3,
    float* __restrict__ out)
{
    __shared__ float x[68];
    __shared__ float h1[32];
    __shared__ float h2[16];
    int lane = threadIdx.x;
    x[lane]      = g_GE[lane] * (1.0f / NNODES);
    x[lane + 32] = g_GE[lane + 32] * (1.0f / NNODES);
    if (lane < 4) x[64 + lane] = TS[lane];
    __syncwarp();
    float a = bk1[lane];
    #pragma unroll 4
    for (int k = 0; k < 68; k++) a += x[k] * Wk1[k * 32 + lane];
    h1[lane] = fmaxf(a, 0.f);
    __syncwarp();
    if (lane < 16) {
        float b = bk2[lane];
        #pragma unroll
        for (int k = 0; k < 32; k++) b += h1[k] * Wk2[k * 16 + lane];
        h2[lane] = fmaxf(b, 0.f);
    }
    __syncwarp();
    if (lane == 0) {
        float raw = bk3[0];
        #pragma unroll
        for (int k = 0; k < 16; k++) raw += h2[k] * Wk3[k];
        float sig = 1.0f / (1.0f + expf(-raw));
        out[NOD] = KMIN + sig * (KMAX - KMIN);
    }
}

// ---------- launcher ----------
extern "C" void kernel_launch(void* const* d_in, const int* in_sizes, int n_in,
                              void* d_out, int out_size)
{
    const float* NF  = (const float*)d_in[0];
    const int*   EI  = (const int*)  d_in[1];
    const float* EF  = (const float*)d_in[2];
    const int*   OD  = (const int*)  d_in[3];
    const float* TS  = (const float*)d_in[4];
    const float* Wn  = (const float*)d_in[5];
    const float* bn  = (const float*)d_in[6];
    const float* We  = (const float*)d_in[7];
    const float* be  = (const float*)d_in[8];
    const float* Wm  = (const float*)d_in[9];
    const float* bm  = (const float*)d_in[10];
    const float* Wu  = (const float*)d_in[11];
    const float* bu  = (const float*)d_in[12];
    const float* Ws1 = (const float*)d_in[13];
    const float* bs1 = (const float*)d_in[14];
    const float* Ws2 = (const float*)d_in[15];
    const float* bs2 = (const float*)d_in[16];
    const float* Wk1 = (const float*)d_in[17];
    const float* bk1 = (const float*)d_in[18];
    const float* Wk2 = (const float*)d_in[19];
    const float* bk2 = (const float*)d_in[20];
    const float* Wk3 = (const float*)d_in[21];
    const float* bk3 = (const float*)d_in[22];
    float* out = (float*)d_out;

    __nv_bfloat16* E;
    float *H0, *H1, *Hm, *AG;
    cudaGetSymbolAddress((void**)&E,  g_Ebf);
    cudaGetSymbolAddress((void**)&H0, g_H0);
    cudaGetSymbolAddress((void**)&H1, g_H1);
    cudaGetSymbolAddress((void**)&Hm, g_Hm);
    cudaGetSymbolAddress((void**)&AG, g_AG);

    const int* src = EI;
    const int* dst = EI + NEDGES;
    const int* ods = OD;
    const int* odd = OD + NOD;

    int nblk = (NNODES + NROWS - 1) / NROWS;

    k_node_proj<<<NNODES / 16, 256>>>(NF, Wn, bn, H0);
    k_edge_proj<<<NEDGES / TE, 256>>>(EF, We, be, E);

    float* Hcur = H0;
    float* Hnext = H1;
    for (int l = 0; l < NLAYERS; l++) {
        const float* Wml = Wm + (size_t)l * 2 * HID * HID;
        const float* bml = bm + (size_t)l * HID;
        const float* Wul = Wu + (size_t)l * 2 * HID * HID;
        const float* bul = bu + (size_t)l * HID;
        k_hm<<<nblk, 128>>>(Hcur, Wml, bml, Hm, AG);
        k_edge_mp<<<NEDGES / TE, 128>>>(E, src, dst, Hm, Wml + HID * HID, AG);
        k_update<<<nblk, 128>>>(Hcur, AG, Wul, bul, Hnext);
        float* t = Hcur; Hcur = Hnext; Hnext = t;
    }

    // scores: reuse Hm as A, AG as B
    k_ab<<<nblk, 128>>>(Hcur, Ws1, Hm, AG);
    k_scores<<<NOD / 8, 256>>>(Hm, AG, ods, odd, bs1, Ws2, bs2, out);

    k_gesum<<<(NNODES + 255) / 256, 256>>>(Hcur);
    k_khead<<<1, 32>>>(TS, Wk1, bk1, Wk2, bk2, Wk3, bk3, out);
}

// round 5
// speedup vs baseline: 2.2046x; 1.4312x over previous
#include <cuda_runtime.h>
#include <cuda_bf16.h>
#include <math.h>

#define NNODES 50000
#define NEDGES 1200000
#define NOD    10000
#define DNODE  16
#define DEDGE  8
#define HID    64
#define NLAYERS 3
#define TE     128
#define NROWS  32
#define NTILES (NEDGES / TE)
#define KMIN   1.0f
#define KMAX   50.0f

// ---------- scratch (device globals; no runtime allocation) ----------
__device__ unsigned char g_Ebf[(size_t)NEDGES * HID * 2];        // SW128 tiles [tile][128x128B]
__device__ unsigned char g_Wbf[(size_t)NLAYERS * HID * HID * 2]; // SW128 B tiles (col-permuted)
__device__ float g_H0[(size_t)NNODES * HID];
__device__ float g_H1[(size_t)NNODES * HID];
__device__ float g_Hm[(size_t)NNODES * HID];
__device__ float g_AG[(size_t)NNODES * HID];
__device__ float g_GE[HID];

// ---------- packed f32x2 helpers ----------
__device__ __forceinline__ unsigned long long pack2(float x, float y) {
    unsigned long long r; asm("mov.b64 %0,{%1,%2};" : "=l"(r) : "f"(x), "f"(y)); return r;
}
__device__ __forceinline__ unsigned long long dup2(float x) {
    unsigned long long r; asm("mov.b64 %0,{%1,%1};" : "=l"(r) : "f"(x)); return r;
}
__device__ __forceinline__ float2 unpack2(unsigned long long v) {
    float2 f; asm("mov.b64 {%0,%1},%2;" : "=f"(f.x), "=f"(f.y) : "l"(v)); return f;
}
__device__ __forceinline__ void fma2(unsigned long long& a,
                                     unsigned long long x, unsigned long long y) {
    asm("fma.rn.f32x2 %0,%1,%2,%0;" : "+l"(a) : "l"(x), "l"(y));
}

// ---------- async / mma helpers ----------
__device__ __forceinline__ unsigned smem_u32(const void* p) {
    unsigned a;
    asm("{.reg .u64 t; cvta.to.shared.u64 t, %1; cvt.u32.u64 %0, t;}" : "=r"(a) : "l"(p));
    return a;
}
__device__ __forceinline__ void cpa16(unsigned s, const void* g) {
    asm volatile("cp.async.cg.shared.global [%0], [%1], 16;" :: "r"(s), "l"(g));
}
__device__ __forceinline__ void ldm4(unsigned& r0, unsigned& r1, unsigned& r2, unsigned& r3,
                                     unsigned addr) {
    asm volatile("ldmatrix.sync.aligned.m8n8.x4.shared.b16 {%0,%1,%2,%3},[%4];"
                 : "=r"(r0), "=r"(r1), "=r"(r2), "=r"(r3) : "r"(addr));
}
__device__ __forceinline__ void mma16816(float* c, unsigned a0, unsigned a1,
                                         unsigned a2, unsigned a3, unsigned b0, unsigned b1) {
    asm volatile("mma.sync.aligned.m16n8k16.row.col.f32.bf16.bf16.f32 "
                 "{%0,%1,%2,%3},{%4,%5,%6,%7},{%8,%9},{%0,%1,%2,%3};"
                 : "+f"(c[0]), "+f"(c[1]), "+f"(c[2]), "+f"(c[3])
                 : "r"(a0), "r"(a1), "r"(a2), "r"(a3), "r"(b0), "r"(b1));
}
__device__ __forceinline__ unsigned sw128(unsigned off) {
    return off ^ ((off >> 3) & 0x70u);
}

// ---------- h0 = relu(NF @ Wn + bn) ----------
__global__ __launch_bounds__(256) void k_node_proj(
    const float* __restrict__ NF, const float* __restrict__ Wn,
    const float* __restrict__ bn, float* __restrict__ H)
{
    __shared__ float Ws[DNODE * HID];
    __shared__ float xs[16][DNODE];
    int tid = threadIdx.x;
    int rl = tid >> 4, j0 = (tid & 15) * 4;
    long r0 = (long)blockIdx.x * 16;
    ((float4*)Ws)[tid] = ((const float4*)Wn)[tid];
    xs[tid >> 4][tid & 15] = NF[r0 * DNODE + tid];
    __syncthreads();
    float4 b = *(const float4*)(bn + j0);
    unsigned long long a0 = pack2(b.x, b.y), a1 = pack2(b.z, b.w);
    #pragma unroll
    for (int k = 0; k < DNODE; k++) {
        unsigned long long ap = dup2(xs[rl][k]);
        const unsigned long long* w = (const unsigned long long*)(Ws + k * HID + j0);
        fma2(a0, ap, w[0]); fma2(a1, ap, w[1]);
    }
    float2 v0 = unpack2(a0), v1 = unpack2(a1);
    *(float4*)(H + (r0 + rl) * HID + j0) =
        make_float4(fmaxf(v0.x,0.f), fmaxf(v0.y,0.f), fmaxf(v1.x,0.f), fmaxf(v1.y,0.f));
}

// ---------- E tile = relu(EF @ We + be), bf16, SW128 row-major [e][k] ----------
__global__ __launch_bounds__(256) void k_edge_proj(
    const float* __restrict__ EF, const float* __restrict__ We,
    const float* __restrict__ be, unsigned char* __restrict__ E)
{
    __shared__ float Ws[DEDGE * HID];
    __shared__ float efs[TE * DEDGE];
    __shared__ __align__(16) unsigned char Es[TE * HID * 2];  // 16KB
    int tid = threadIdx.x;
    long e0g = (long)blockIdx.x * TE;
    if (tid < 128) ((float4*)Ws)[tid] = ((const float4*)We)[tid];
    ((float4*)efs)[tid] = ((const float4*)(EF + e0g * DEDGE))[tid];
    __syncthreads();
    int jt = tid & 15, et = tid >> 4;
    int j0 = jt * 4;
    float4 b = *(const float4*)(be + j0);
    #pragma unroll
    for (int ee = 0; ee < 8; ee++) {
        int e = et * 8 + ee;
        unsigned long long a0 = pack2(b.x, b.y), a1 = pack2(b.z, b.w);
        const float* x = efs + e * DEDGE;
        #pragma unroll
        for (int k = 0; k < DEDGE; k++) {
            unsigned long long ap = dup2(x[k]);
            const unsigned long long* w = (const unsigned long long*)(Ws + k * HID + j0);
            fma2(a0, ap, w[0]); fma2(a1, ap, w[1]);
        }
        float2 v0 = unpack2(a0), v1 = unpack2(a1);
        __nv_bfloat162 p0 = __floats2bfloat162_rn(fmaxf(v0.x,0.f), fmaxf(v0.y,0.f));
        __nv_bfloat162 p1 = __floats2bfloat162_rn(fmaxf(v1.x,0.f), fmaxf(v1.y,0.f));
        unsigned off = (unsigned)e * 128u + (unsigned)j0 * 2u;
        unsigned sw = sw128(off);
        *(unsigned*)(Es + sw)     = *(unsigned*)&p0;
        *(unsigned*)(Es + sw + 4) = *(unsigned*)&p1;
    }
    __syncthreads();
    uint4* dst4 = (uint4*)(E + (size_t)blockIdx.x * 16384);
    const uint4* src4 = (const uint4*)Es;
    #pragma unroll
    for (int i = 0; i < 4; i++) dst4[tid + i * 256] = src4[tid + i * 256];
}

// ---------- Wbot -> bf16 B tile [n_phys][k], SW128, column-permuted ----------
// physical row p holds logical output column L = ((p&7)>>1)*16 + (p>>3)*2 + (p&1)
__global__ void k_wconv(const float* __restrict__ Wm, unsigned char* __restrict__ Wbf)
{
    int l = blockIdx.x;
    const float* W = Wm + (size_t)l * 2 * HID * HID + (size_t)HID * HID;  // bottom half [k][n]
    unsigned char* out = Wbf + (size_t)l * HID * HID * 2;
    for (int i = threadIdx.x; i < HID * HID; i += blockDim.x) {
        int p = i >> 6, k = i & 63;
        int L = ((p & 7) >> 1) * 16 + (p >> 3) * 2 + (p & 1);
        unsigned off = (unsigned)p * 128u + (unsigned)k * 2u;
        *(__nv_bfloat16*)(out + sw128(off)) = __float2bfloat16(W[k * HID + L]);
    }
}

// ---------- Hm = h @ Wm_top + bm (no relu); AGG = 0 ----------
__global__ __launch_bounds__(128) void k_hm(
    const float* __restrict__ H, const float* __restrict__ Wtop,
    const float* __restrict__ bm, float* __restrict__ Hm, float* __restrict__ AGG)
{
    __shared__ float Ws[HID * HID];
    __shared__ float xs[NROWS * HID];
    int tid = threadIdx.x;
    long r0 = (long)blockIdx.x * NROWS;
    int nrow = NNODES - (int)r0; if (nrow > NROWS) nrow = NROWS;
    #pragma unroll
    for (int i = 0; i < 8; i++)
        ((float4*)Ws)[tid + i * 128] = ((const float4*)Wtop)[tid + i * 128];
    #pragma unroll
    for (int i = 0; i < 4; i++) {
        int idx = tid + i * 128;
        if ((idx >> 4) < nrow) ((float4*)xs)[idx] = ((const float4*)(H + r0 * HID))[idx];
    }
    __syncthreads();
    int jt = tid & 15, rt = tid >> 4;
    int j0 = jt * 4, rb = rt * 4;
    float4 b = *(const float4*)(bm + j0);
    unsigned long long acc[4][2];
    #pragma unroll
    for (int i = 0; i < 4; i++) { acc[i][0] = pack2(b.x, b.y); acc[i][1] = pack2(b.z, b.w); }
    #pragma unroll 4
    for (int k = 0; k < HID; k++) {
        const unsigned long long* w = (const unsigned long long*)(Ws + k * HID + j0);
        unsigned long long w0 = w[0], w1 = w[1];
        #pragma unroll
        for (int i = 0; i < 4; i++) {
            unsigned long long ap = dup2(xs[(rb + i) * HID + k]);
            fma2(acc[i][0], ap, w0); fma2(acc[i][1], ap, w1);
        }
    }
    #pragma unroll
    for (int i = 0; i < 4; i++) {
        if (rb + i < nrow) {
            float2 v0 = unpack2(acc[i][0]), v1 = unpack2(acc[i][1]);
            long o = (r0 + rb + i) * HID + j0;
            *(float4*)(Hm + o)  = make_float4(v0.x, v0.y, v1.x, v1.y);
            *(float4*)(AGG + o) = make_float4(0.f, 0.f, 0.f, 0.f);
        }
    }
}

// ---------- per-tile mma.sync message GEMM + fused gather/scatter ----------
__global__ void __launch_bounds__(128)
k_edge_mp(const unsigned char* __restrict__ Eg, const int* __restrict__ src,
          const int* __restrict__ dst, const float* __restrict__ Hm,
          const unsigned char* __restrict__ Wbf, float* __restrict__ AGG)
{
    __shared__ __align__(1024) unsigned char SB[24576];  // E @0 (16KB), B @16384 (8KB)
    int tid = threadIdx.x;
    int w = tid >> 5, lane = tid & 31;
    unsigned sb = smem_u32(SB);

    // load E tile + B tile
    {
        const unsigned char* g = Eg + (size_t)blockIdx.x * 16384;
        #pragma unroll
        for (int i = 0; i < 8; i++)
            cpa16(sb + tid * 16 + i * 2048, g + tid * 16 + i * 2048);
        #pragma unroll
        for (int i = 0; i < 4; i++)
            cpa16(sb + 16384u + tid * 16 + i * 2048, Wbf + tid * 16 + i * 2048);
    }
    asm volatile("cp.async.commit_group;" ::: "memory");
    asm volatile("cp.async.wait_group 0;" ::: "memory");
    __syncthreads();

    float acc[2][8][4];
    #pragma unroll
    for (int mt = 0; mt < 2; mt++)
        #pragma unroll
        for (int t = 0; t < 8; t++)
            #pragma unroll
            for (int c = 0; c < 4; c++) acc[mt][t][c] = 0.f;

    int q = lane >> 3, rloc = lane & 7;
    #pragma unroll
    for (int kk = 0; kk < 4; kk++) {
        // B fragments for this k-step: 8 ntiles x 2 regs via 4 ldmatrix.x4
        unsigned bf[16];
        #pragma unroll
        for (int tp = 0; tp < 4; tp++) {
            unsigned row = (unsigned)((2 * tp + (q >> 1)) * 8 + rloc);
            unsigned colb = (unsigned)(kk * 32 + (q & 1) * 16);
            unsigned addr = sb + 16384u + sw128(row * 128u + colb);
            ldm4(bf[4*tp+0], bf[4*tp+1], bf[4*tp+2], bf[4*tp+3], addr);
        }
        #pragma unroll
        for (int mt = 0; mt < 2; mt++) {
            unsigned a0, a1, a2, a3;
            unsigned row = (unsigned)(w * 32 + mt * 16 + (q & 1) * 8 + rloc);
            unsigned colb = (unsigned)(kk * 32 + (q >> 1) * 16);
            ldm4(a0, a1, a2, a3, sb + sw128(row * 128u + colb));
            #pragma unroll
            for (int t = 0; t < 8; t++)
                mma16816(acc[mt][t], a0, a1, a2, a3, bf[2*t], bf[2*t+1]);
        }
    }

    // epilogue: fused Hm gather + relu + scatter (col-permuted B makes cols contiguous)
    int i4 = lane >> 2, j = lane & 3;
    #pragma unroll
    for (int mt = 0; mt < 2; mt++) {
        #pragma unroll
        for (int rr = 0; rr < 2; rr++) {
            int eloc = w * 32 + mt * 16 + rr * 8 + i4;
            long eg = (long)blockIdx.x * TE + eloc;
            int s = src[eg], d = dst[eg];
            const float4* hm = (const float4*)(Hm + (long)s * HID + j * 16);
            float* ag = AGG + (long)d * HID + j * 16;
            #pragma unroll
            for (int c = 0; c < 4; c++) {
                float4 h = hm[c];
                float v0 = fmaxf(acc[mt][2*c  ][rr*2+0] + h.x, 0.f);
                float v1 = fmaxf(acc[mt][2*c  ][rr*2+1] + h.y, 0.f);
                float v2 = fmaxf(acc[mt][2*c+1][rr*2+0] + h.z, 0.f);
                float v3 = fmaxf(acc[mt][2*c+1][rr*2+1] + h.w, 0.f);
                asm volatile("red.global.add.v4.f32 [%0], {%1,%2,%3,%4};"
                    :: "l"(ag + c * 4), "f"(v0), "f"(v1), "f"(v2), "f"(v3) : "memory");
            }
        }
    }
}

// ---------- h' = relu([h, agg] @ Wu + bu) + h ----------
__global__ __launch_bounds__(128) void k_update(
    const float* __restrict__ Hin, const float* __restrict__ AGG,
    const float* __restrict__ Wu, const float* __restrict__ bu, float* __restrict__ Hout)
{
    __shared__ float Ws[2 * HID * HID];
    __shared__ float xs[NROWS * HID];
    __shared__ float as_[NROWS * HID];
    int tid = threadIdx.x;
    long r0 = (long)blockIdx.x * NROWS;
    int nrow = NNODES - (int)r0; if (nrow > NROWS) nrow = NROWS;
    #pragma unroll
    for (int i = 0; i < 16; i++)
        ((float4*)Ws)[tid + i * 128] = ((const float4*)Wu)[tid + i * 128];
    #pragma unroll
    for (int i = 0; i < 4; i++) {
        int idx = tid + i * 128;
        if ((idx >> 4) < nrow) {
            ((float4*)xs)[idx]  = ((const float4*)(Hin + r0 * HID))[idx];
            ((float4*)as_)[idx] = ((const float4*)(AGG + r0 * HID))[idx];
        }
    }
    __syncthreads();
    int jt = tid & 15, rt = tid >> 4;
    int j0 = jt * 4, rb = rt * 4;
    float4 b = *(const float4*)(bu + j0);
    unsigned long long acc[4][2];
    #pragma unroll
    for (int i = 0; i < 4; i++) { acc[i][0] = pack2(b.x, b.y); acc[i][1] = pack2(b.z, b.w); }
    #pragma unroll 4
    for (int k = 0; k < HID; k++) {
        const unsigned long long* w = (const unsigned long long*)(Ws + k * HID + j0);
        unsigned long long w0 = w[0], w1 = w[1];
        #pragma unroll
        for (int i = 0; i < 4; i++) {
            unsigned long long ap = dup2(xs[(rb + i) * HID + k]);
            fma2(acc[i][0], ap, w0); fma2(acc[i][1], ap, w1);
        }
    }
    #pragma unroll 4
    for (int k = 0; k < HID; k++) {
        const unsigned long long* w = (const unsigned long long*)(Ws + (HID + k) * HID + j0);
        unsigned long long w0 = w[0], w1 = w[1];
        #pragma unroll
        for (int i = 0; i < 4; i++) {
            unsigned long long ap = dup2(as_[(rb + i) * HID + k]);
            fma2(acc[i][0], ap, w0); fma2(acc[i][1], ap, w1);
        }
    }
    #pragma unroll
    for (int i = 0; i < 4; i++) {
        if (rb + i < nrow) {
            float2 v0 = unpack2(acc[i][0]), v1 = unpack2(acc[i][1]);
            const float* xr = xs + (rb + i) * HID + j0;
            long o = (r0 + rb + i) * HID + j0;
            *(float4*)(Hout + o) = make_float4(
                fmaxf(v0.x,0.f) + xr[0], fmaxf(v0.y,0.f) + xr[1],
                fmaxf(v1.x,0.f) + xr[2], fmaxf(v1.y,0.f) + xr[3]);
        }
    }
}

// ---------- A = h @ Ws1_top ; B = h @ Ws1_bot ----------
__global__ __launch_bounds__(128) void k_ab(
    const float* __restrict__ H, const float* __restrict__ Ws1,
    float* __restrict__ A, float* __restrict__ B)
{
    __shared__ float Ws[2 * HID * HID];
    __shared__ float xs[NROWS * HID];
    int tid = threadIdx.x;
    long r0 = (long)blockIdx.x * NROWS;
    int nrow = NNODES - (int)r0; if (nrow > NROWS) nrow = NROWS;
    #pragma unroll
    for (int i = 0; i < 16; i++)
        ((float4*)Ws)[tid + i * 128] = ((const float4*)Ws1)[tid + i * 128];
    #pragma unroll
    for (int i = 0; i < 4; i++) {
        int idx = tid + i * 128;
        if ((idx >> 4) < nrow) ((float4*)xs)[idx] = ((const float4*)(H + r0 * HID))[idx];
    }
    __syncthreads();
    int jt = tid & 15, rt = tid >> 4;
    int j0 = jt * 4, rb = rt * 4;
    unsigned long long aA[4][2], aB[4][2];
    #pragma unroll
    for (int i = 0; i < 4; i++) { aA[i][0]=0; aA[i][1]=0; aB[i][0]=0; aB[i][1]=0; }
    #pragma unroll 4
    for (int k = 0; k < HID; k++) {
        const unsigned long long* wt = (const unsigned long long*)(Ws + k * HID + j0);
        const unsigned long long* wb = (const unsigned long long*)(Ws + (HID + k) * HID + j0);
        unsigned long long t0 = wt[0], t1 = wt[1], b0 = wb[0], b1 = wb[1];
        #pragma unroll
        for (int i = 0; i < 4; i++) {
            unsigned long long ap = dup2(xs[(rb + i) * HID + k]);
            fma2(aA[i][0], ap, t0); fma2(aA[i][1], ap, t1);
            fma2(aB[i][0], ap, b0); fma2(aB[i][1], ap, b1);
        }
    }
    #pragma unroll
    for (int i = 0; i < 4; i++) {
        if (rb + i < nrow) {
            float2 x0 = unpack2(aA[i][0]), x1 = unpack2(aA[i][1]);
            float2 y0 = unpack2(aB[i][0]), y1 = unpack2(aB[i][1]);
            long o = (r0 + rb + i) * HID + j0;
            *(float4*)(A + o) = make_float4(x0.x, x0.y, x1.x, x1.y);
            *(float4*)(B + o) = make_float4(y0.x, y0.y, y1.x, y1.y);
        }
    }
}

// ---------- per-OD scores (also zeroes g_GE from block 0) ----------
__global__ __launch_bounds__(256) void k_scores(
    const float* __restrict__ A, const float* __restrict__ B,
    const int* __restrict__ ods, const int* __restrict__ odd,
    const float* __restrict__ bs1, const float* __restrict__ Ws2,
    const float* __restrict__ bs2, float* __restrict__ out)
{
    if (blockIdx.x == 0 && threadIdx.x < HID) g_GE[threadIdx.x] = 0.f;
    int warp = threadIdx.x >> 5, lane = threadIdx.x & 31;
    int p = blockIdx.x * 8 + warp;
    int s = ods[p], d = odd[p];
    const float* Ar = A + (long)s * HID;
    const float* Br = B + (long)d * HID;
    int j1 = lane, j2 = lane + 32;
    float t1 = fmaxf(Ar[j1] + Br[j1] + bs1[j1], 0.f);
    float t2 = fmaxf(Ar[j2] + Br[j2] + bs1[j2], 0.f);
    float v = t1 * Ws2[j1] + t2 * Ws2[j2];
    #pragma unroll
    for (int o = 16; o > 0; o >>= 1) v += __shfl_down_sync(0xffffffffu, v, o);
    if (lane == 0) out[p] = v + bs2[0];
}

// ---------- graph embed sum ----------
__global__ __launch_bounds__(256) void k_gesum(const float* __restrict__ H)
{
    __shared__ float part[4][HID];
    int tid = threadIdx.x;
    int j = tid & 63, g = tid >> 6;
    long base = (long)blockIdx.x * 256 + g;
    float acc = 0.f;
    #pragma unroll 4
    for (int i = 0; i < 64; i++) {
        long r = base + (long)i * 4;
        if (r < NNODES) acc += H[r * HID + j];
    }
    part[g][j] = acc;
    __syncthreads();
    if (g == 0) {
        float s = part[0][j] + part[1][j] + part[2][j] + part[3][j];
        atomicAdd(&g_GE[j], s);
    }
}

// ---------- dynamic-K head (single warp) ----------
__global__ void k_khead(
    const float* __restrict__ TS,
    const float* __restrict__ Wk1, const float* __restrict__ bk1,
    const float* __restrict__ Wk2, const float* __restrict__ bk2,
    const float* __restrict__ Wk3, const float* __restrict__ bk3,
    float* __restrict__ out)
{
    __shared__ float x[68];
    __shared__ float h1[32];
    __shared__ float h2[16];
    int lane = threadIdx.x;
    x[lane]      = g_GE[lane] * (1.0f / NNODES);
    x[lane + 32] = g_GE[lane + 32] * (1.0f / NNODES);
    if (lane < 4) x[64 + lane] = TS[lane];
    __syncwarp();
    float a = bk1[lane];
    #pragma unroll 4
    for (int k = 0; k < 68; k++) a += x[k] * Wk1[k * 32 + lane];
    h1[lane] = fmaxf(a, 0.f);
    __syncwarp();
    if (lane < 16) {
        float b = bk2[lane];
        #pragma unroll
        for (int k = 0; k < 32; k++) b += h1[k] * Wk2[k * 16 + lane];
        h2[lane] = fmaxf(b, 0.f);
    }
    __syncwarp();
    if (lane == 0) {
        float raw = bk3[0];
        #pragma unroll
        for (int k = 0; k < 16; k++) raw += h2[k] * Wk3[k];
        float sig = 1.0f / (1.0f + expf(-raw));
        out[NOD] = KMIN + sig * (KMAX - KMIN);
    }
}

// ---------- launcher ----------
extern "C" void kernel_launch(void* const* d_in, const int* in_sizes, int n_in,
                              void* d_out, int out_size)
{
    const float* NF  = (const float*)d_in[0];
    const int*   EI  = (const int*)  d_in[1];
    const float* EF  = (const float*)d_in[2];
    const int*   OD  = (const int*)  d_in[3];
    const float* TS  = (const float*)d_in[4];
    const float* Wn  = (const float*)d_in[5];
    const float* bn  = (const float*)d_in[6];
    const float* We  = (const float*)d_in[7];
    const float* be  = (const float*)d_in[8];
    const float* Wm  = (const float*)d_in[9];
    const float* bm  = (const float*)d_in[10];
    const float* Wu  = (const float*)d_in[11];
    const float* bu  = (const float*)d_in[12];
    const float* Ws1 = (const float*)d_in[13];
    const float* bs1 = (const float*)d_in[14];
    const float* Ws2 = (const float*)d_in[15];
    const float* bs2 = (const float*)d_in[16];
    const float* Wk1 = (const float*)d_in[17];
    const float* bk1 = (const float*)d_in[18];
    const float* Wk2 = (const float*)d_in[19];
    const float* bk2 = (const float*)d_in[20];
    const float* Wk3 = (const float*)d_in[21];
    const float* bk3 = (const float*)d_in[22];
    float* out = (float*)d_out;

    unsigned char *E, *Wbf;
    float *H0, *H1, *Hm, *AG;
    cudaGetSymbolAddress((void**)&E,   g_Ebf);
    cudaGetSymbolAddress((void**)&Wbf, g_Wbf);
    cudaGetSymbolAddress((void**)&H0,  g_H0);
    cudaGetSymbolAddress((void**)&H1,  g_H1);
    cudaGetSymbolAddress((void**)&Hm,  g_Hm);
    cudaGetSymbolAddress((void**)&AG,  g_AG);

    const int* src = EI;
    const int* dst = EI + NEDGES;
    const int* ods = OD;
    const int* odd = OD + NOD;

    int nblk = (NNODES + NROWS - 1) / NROWS;

    k_node_proj<<<NNODES / 16, 256>>>(NF, Wn, bn, H0);
    k_edge_proj<<<NEDGES / TE, 256>>>(EF, We, be, E);
    k_wconv<<<NLAYERS, 256>>>(Wm, Wbf);

    float* Hcur = H0;
    float* Hnext = H1;
    for (int l = 0; l < NLAYERS; l++) {
        const float* Wml = Wm + (size_t)l * 2 * HID * HID;
        const float* bml = bm + (size_t)l * HID;
        const float* Wul = Wu + (size_t)l * 2 * HID * HID;
        const float* bul = bu + (size_t)l * HID;
        k_hm<<<nblk, 128>>>(Hcur, Wml, bml, Hm, AG);
        k_edge_mp<<<NTILES, 128>>>(E, src, dst, Hm, Wbf + (size_t)l * HID * HID * 2, AG);
        k_update<<<nblk, 128>>>(Hcur, AG, Wul, bul, Hnext);
        float* t = Hcur; Hcur = Hnext; Hnext = t;
    }

    // scores: reuse Hm as A, AG as B
    k_ab<<<nblk, 128>>>(Hcur, Ws1, Hm, AG);
    k_scores<<<NOD / 8, 256>>>(Hm, AG, ods, odd, bs1, Ws2, bs2, out);

    k_gesum<<<(NNODES + 255) / 256, 256>>>(Hcur);
    k_khead<<<1, 32>>>(TS, Wk1, bk1, Wk2, bk2, Wk3, bk3, out);
}

// round 8
// speedup vs baseline: 2.4535x; 1.1129x over previous
#include <cuda_runtime.h>
#include <cuda_bf16.h>
#include <math.h>

#define NNODES 50000
#define NOD    10000
#define NEDGES 1200000
#define DNODE  16
#define DEDGE  8
#define HID    64
#define NLAYERS 3
#define TE     128
#define NTILES (NEDGES / TE)
#define NTILE_N 391
#define KMIN   1.0f
#define KMAX   50.0f

// ---------- scratch ----------
__device__ unsigned char g_Ebf[(size_t)NEDGES * HID * 2];     // SW128 edge tiles (bf16)
__device__ unsigned char g_Hbf[(size_t)NTILE_N * 32768];      // node tiles: hi(16K)+lo(16K)
__device__ unsigned char g_Wt [(size_t)28 * 8192];            // W tiles: [logical*2]=hi,[+1]=lo
__device__ float g_H0[(size_t)NNODES * HID];
__device__ float g_H1[(size_t)NNODES * HID];
__device__ float g_Hm[(size_t)NNODES * HID];
__device__ float g_AG[(size_t)NNODES * HID];
__device__ float g_GE[HID];

// ---------- packed f32x2 helpers ----------
__device__ __forceinline__ unsigned long long pack2(float x, float y) {
    unsigned long long r; asm("mov.b64 %0,{%1,%2};" : "=l"(r) : "f"(x), "f"(y)); return r;
}
__device__ __forceinline__ unsigned long long dup2(float x) {
    unsigned long long r; asm("mov.b64 %0,{%1,%1};" : "=l"(r) : "f"(x)); return r;
}
__device__ __forceinline__ float2 unpack2(unsigned long long v) {
    float2 f; asm("mov.b64 {%0,%1},%2;" : "=f"(f.x), "=f"(f.y) : "l"(v)); return f;
}
__device__ __forceinline__ void fma2(unsigned long long& a,
                                     unsigned long long x, unsigned long long y) {
    asm("fma.rn.f32x2 %0,%1,%2,%0;" : "+l"(a) : "l"(x), "l"(y));
}

// ---------- async / mma helpers ----------
__device__ __forceinline__ unsigned smem_u32(const void* p) {
    unsigned a;
    asm("{.reg .u64 t; cvta.to.shared.u64 t, %1; cvt.u32.u64 %0, t;}" : "=r"(a) : "l"(p));
    return a;
}
__device__ __forceinline__ void cpa16(unsigned s, const void* g) {
    asm volatile("cp.async.cg.shared.global [%0], [%1], 16;" :: "r"(s), "l"(g));
}
__device__ __forceinline__ void ldm4(unsigned& r0, unsigned& r1, unsigned& r2, unsigned& r3,
                                     unsigned addr) {
    asm volatile("ldmatrix.sync.aligned.m8n8.x4.shared.b16 {%0,%1,%2,%3},[%4];"
                 : "=r"(r0), "=r"(r1), "=r"(r2), "=r"(r3) : "r"(addr));
}
__device__ __forceinline__ void mma16816(float* c, unsigned a0, unsigned a1,
                                         unsigned a2, unsigned a3, unsigned b0, unsigned b1) {
    asm volatile("mma.sync.aligned.m16n8k16.row.col.f32.bf16.bf16.f32 "
                 "{%0,%1,%2,%3},{%4,%5,%6,%7},{%8,%9},{%0,%1,%2,%3};"
                 : "+f"(c[0]), "+f"(c[1]), "+f"(c[2]), "+f"(c[3])
                 : "r"(a0), "r"(a1), "r"(a2), "r"(a3), "r"(b0), "r"(b1));
}
__device__ __forceinline__ unsigned sw128(unsigned off) {
    return off ^ ((off >> 3) & 0x70u);
}
// hi/lo split store into two swizzled smem tiles (8 bytes each at sw offset)
__device__ __forceinline__ void st_hilo(unsigned sb_hi, unsigned sb_lo, unsigned sw,
                                        float v0, float v1, float v2, float v3) {
    __nv_bfloat16 h0 = __float2bfloat16(v0), h1 = __float2bfloat16(v1);
    __nv_bfloat16 h2 = __float2bfloat16(v2), h3 = __float2bfloat16(v3);
    __nv_bfloat16 l0 = __float2bfloat16(v0 - __bfloat162float(h0));
    __nv_bfloat16 l1 = __float2bfloat16(v1 - __bfloat162float(h1));
    __nv_bfloat16 l2 = __float2bfloat16(v2 - __bfloat162float(h2));
    __nv_bfloat16 l3 = __float2bfloat16(v3 - __bfloat162float(h3));
    unsigned hp0 = ((unsigned)*(unsigned short*)&h1 << 16) | *(unsigned short*)&h0;
    unsigned hp1 = ((unsigned)*(unsigned short*)&h3 << 16) | *(unsigned short*)&h2;
    unsigned lp0 = ((unsigned)*(unsigned short*)&l1 << 16) | *(unsigned short*)&l0;
    unsigned lp1 = ((unsigned)*(unsigned short*)&l3 << 16) | *(unsigned short*)&l2;
    asm volatile("st.shared.v2.b32 [%0],{%1,%2};" :: "r"(sb_hi + sw), "r"(hp0), "r"(hp1) : "memory");
    asm volatile("st.shared.v2.b32 [%0],{%1,%2};" :: "r"(sb_lo + sw), "r"(lp0), "r"(lp1) : "memory");
}

// shared 128x64x64 mma core
__device__ __forceinline__ void mma_core(unsigned abase, unsigned bbase,
                                         float acc[2][8][4], int w, int lane)
{
    int q = lane >> 3, rloc = lane & 7;
    #pragma unroll
    for (int kk = 0; kk < 4; kk++) {
        unsigned bf[16];
        #pragma unroll
        for (int tp = 0; tp < 4; tp++) {
            unsigned row = (unsigned)((2 * tp + (q >> 1)) * 8 + rloc);
            unsigned colb = (unsigned)(kk * 32 + (q & 1) * 16);
            ldm4(bf[4*tp+0], bf[4*tp+1], bf[4*tp+2], bf[4*tp+3],
                 bbase + sw128(row * 128u + colb));
        }
        #pragma unroll
        for (int mt = 0; mt < 2; mt++) {
            unsigned a0, a1, a2, a3;
            unsigned row = (unsigned)(w * 32 + mt * 16 + (q & 1) * 8 + rloc);
            unsigned colb = (unsigned)(kk * 32 + (q >> 1) * 16);
            ldm4(a0, a1, a2, a3, abase + sw128(row * 128u + colb));
            #pragma unroll
            for (int t = 0; t < 8; t++)
                mma16816(acc[mt][t], a0, a1, a2, a3, bf[2*t], bf[2*t+1]);
        }
    }
}

// ---------- h0 = relu(NF @ Wn + bn) -> H fp32 + Hbf hi/lo tile ----------
__global__ __launch_bounds__(256) void k_node_proj(
    const float* __restrict__ NF, const float* __restrict__ Wn,
    const float* __restrict__ bn, float* __restrict__ H, unsigned char* __restrict__ Hbf)
{
    __shared__ float Ws[DNODE * HID];
    __shared__ float efs[128 * DNODE];
    __shared__ __align__(16) unsigned char Es[32768];   // hi@0, lo@16384
    int tid = threadIdx.x;
    long r0 = (long)blockIdx.x * 128;
    ((float4*)Ws)[tid] = ((const float4*)Wn)[tid];
    #pragma unroll
    for (int i = 0; i < 2; i++) {
        int idx = tid + i * 256;
        long gr = r0 + (idx >> 2);
        ((float4*)efs)[idx] = (gr < NNODES) ? ((const float4*)NF)[gr * 4 + (idx & 3)]
                                            : make_float4(0.f, 0.f, 0.f, 0.f);
    }
    __syncthreads();
    unsigned es = smem_u32(Es);
    int jt = tid & 15, et = tid >> 4;
    int j0 = jt * 4;
    float4 b = *(const float4*)(bn + j0);
    #pragma unroll
    for (int ee = 0; ee < 8; ee++) {
        int e = et * 8 + ee;
        long gr = r0 + e;
        unsigned long long a0 = pack2(b.x, b.y), a1 = pack2(b.z, b.w);
        const float* x = efs + e * DNODE;
        #pragma unroll
        for (int k = 0; k < DNODE; k++) {
            unsigned long long ap = dup2(x[k]);
            const unsigned long long* w = (const unsigned long long*)(Ws + k * HID + j0);
            fma2(a0, ap, w[0]); fma2(a1, ap, w[1]);
        }
        float2 v0 = unpack2(a0), v1 = unpack2(a1);
        float o0 = fmaxf(v0.x,0.f), o1 = fmaxf(v0.y,0.f);
        float o2 = fmaxf(v1.x,0.f), o3 = fmaxf(v1.y,0.f);
        if (gr >= NNODES) { o0 = o1 = o2 = o3 = 0.f; }
        else *(float4*)(H + gr * HID + j0) = make_float4(o0, o1, o2, o3);
        unsigned sw = sw128((unsigned)e * 128u + (unsigned)j0 * 2u);
        st_hilo(es, es + 16384u, sw, o0, o1, o2, o3);
    }
    __syncthreads();
    uint4* dst4 = (uint4*)(Hbf + (size_t)blockIdx.x * 32768);
    const uint4* src4 = (const uint4*)Es;
    #pragma unroll
    for (int i = 0; i < 8; i++) dst4[tid + i * 256] = src4[tid + i * 256];
}

// ---------- E tile = relu(EF @ We + be), bf16 single, SW128 ----------
__global__ __launch_bounds__(256) void k_edge_proj(
    const float* __restrict__ EF, const float* __restrict__ We,
    const float* __restrict__ be, unsigned char* __restrict__ E)
{
    __shared__ float Ws[DEDGE * HID];
    __shared__ float efs[TE * DEDGE];
    __shared__ __align__(16) unsigned char Es[16384];
    int tid = threadIdx.x;
    long e0g = (long)blockIdx.x * TE;
    if (tid < 128) ((float4*)Ws)[tid] = ((const float4*)We)[tid];
    ((float4*)efs)[tid] = ((const float4*)(EF + e0g * DEDGE))[tid];
    __syncthreads();
    int jt = tid & 15, et = tid >> 4;
    int j0 = jt * 4;
    float4 b = *(const float4*)(be + j0);
    #pragma unroll
    for (int ee = 0; ee < 8; ee++) {
        int e = et * 8 + ee;
        unsigned long long a0 = pack2(b.x, b.y), a1 = pack2(b.z, b.w);
        const float* x = efs + e * DEDGE;
        #pragma unroll
        for (int k = 0; k < DEDGE; k++) {
            unsigned long long ap = dup2(x[k]);
            const unsigned long long* w = (const unsigned long long*)(Ws + k * HID + j0);
            fma2(a0, ap, w[0]); fma2(a1, ap, w[1]);
        }
        float2 v0 = unpack2(a0), v1 = unpack2(a1);
        __nv_bfloat162 p0 = __floats2bfloat162_rn(fmaxf(v0.x,0.f), fmaxf(v0.y,0.f));
        __nv_bfloat162 p1 = __floats2bfloat162_rn(fmaxf(v1.x,0.f), fmaxf(v1.y,0.f));
        unsigned sw = sw128((unsigned)e * 128u + (unsigned)j0 * 2u);
        *(unsigned*)(Es + sw)     = *(unsigned*)&p0;
        *(unsigned*)(Es + sw + 4) = *(unsigned*)&p1;
    }
    __syncthreads();
    uint4* dst4 = (uint4*)(E + (size_t)blockIdx.x * 16384);
    const uint4* src4 = (const uint4*)Es;
    #pragma unroll
    for (int i = 0; i < 4; i++) dst4[tid + i * 256] = src4[tid + i * 256];
}

// ---------- all W -> col-permuted SW128 hi/lo tiles ----------
// logical: 0-2 Wm_top[l], 3-5 Wm_bot[l], 6-11 Wu[l]{top,bot}, 12-13 Ws1{top,bot}
__global__ void k_wconv(const float* __restrict__ Wm, const float* __restrict__ Wu,
                        const float* __restrict__ Ws1, unsigned char* __restrict__ Wt)
{
    int b = blockIdx.x;
    const float* src;
    if (b < 3)       src = Wm + (size_t)b * 2 * HID * HID;
    else if (b < 6)  src = Wm + (size_t)(b - 3) * 2 * HID * HID + (size_t)HID * HID;
    else if (b < 12) src = Wu + (size_t)((b - 6) >> 1) * 2 * HID * HID
                              + (size_t)((b - 6) & 1) * HID * HID;
    else             src = Ws1 + (size_t)(b - 12) * HID * HID;
    unsigned char* ohi = Wt + (size_t)(2 * b) * 8192;
    unsigned char* olo = ohi + 8192;
    for (int i = threadIdx.x; i < HID * HID; i += blockDim.x) {
        int p = i >> 6, k = i & 63;
        int L = ((p & 7) >> 1) * 16 + (p >> 3) * 2 + (p & 1);
        float v = src[k * HID + L];
        __nv_bfloat16 hi = __float2bfloat16(v);
        __nv_bfloat16 lo = __float2bfloat16(v - __bfloat162float(hi));
        unsigned sw = sw128((unsigned)p * 128u + (unsigned)k * 2u);
        *(__nv_bfloat16*)(ohi + sw) = hi;
        *(__nv_bfloat16*)(olo + sw) = lo;
    }
}

// ---------- Hm = h @ Wm_top + bm (3-pass mma); AGG = 0 ----------
__global__ void __launch_bounds__(128) k_hm(
    const unsigned char* __restrict__ Hbf, const unsigned char* __restrict__ Wt,
    const float* __restrict__ bm, float* __restrict__ Hm, float* __restrict__ AGG)
{
    __shared__ __align__(1024) unsigned char SB[49152]; // Ahi@0 Alo@16384 Whi@32768 Wlo@40960
    int tid = threadIdx.x, w = tid >> 5, lane = tid & 31;
    unsigned sb = smem_u32(SB);
    const unsigned char* g = Hbf + (size_t)blockIdx.x * 32768;
    #pragma unroll
    for (int i = 0; i < 16; i++) cpa16(sb + tid * 16 + i * 2048, g + tid * 16 + i * 2048);
    #pragma unroll
    for (int i = 0; i < 8; i++)
        cpa16(sb + 32768u + tid * 16 + i * 2048, Wt + tid * 16 + i * 2048);
    asm volatile("cp.async.commit_group;\ncp.async.wait_group 0;" ::: "memory");
    __syncthreads();

    float acc[2][8][4];
    #pragma unroll
    for (int mt = 0; mt < 2; mt++) for (int t = 0; t < 8; t++)
        for (int c = 0; c < 4; c++) acc[mt][t][c] = 0.f;
    mma_core(sb,          sb + 32768u, acc, w, lane);   // Ahi Whi
    mma_core(sb,          sb + 40960u, acc, w, lane);   // Ahi Wlo
    mma_core(sb + 16384u, sb + 32768u, acc, w, lane);   // Alo Whi

    long r0 = (long)blockIdx.x * 128;
    int i4 = lane >> 2, j = lane & 3;
    #pragma unroll
    for (int mt = 0; mt < 2; mt++) {
        #pragma unroll
        for (int rr = 0; rr < 2; rr++) {
            long gr = r0 + w * 32 + mt * 16 + rr * 8 + i4;
            if (gr < NNODES) {
                float* hm = Hm + gr * HID + j * 16;
                float* ag = AGG + gr * HID + j * 16;
                #pragma unroll
                for (int c = 0; c < 4; c++) {
                    float4 bb = *(const float4*)(bm + j * 16 + c * 4);
                    *(float4*)(hm + c * 4) = make_float4(
                        acc[mt][2*c][rr*2+0] + bb.x, acc[mt][2*c][rr*2+1] + bb.y,
                        acc[mt][2*c+1][rr*2+0] + bb.z, acc[mt][2*c+1][rr*2+1] + bb.w);
                    *(float4*)(ag + c * 4) = make_float4(0.f, 0.f, 0.f, 0.f);
                }
            }
        }
    }
}

// ---------- per-tile mma message GEMM + fused gather/scatter ----------
__global__ void __launch_bounds__(128)
k_edge_mp(const unsigned char* __restrict__ Eg, const int* __restrict__ src,
          const int* __restrict__ dst, const float* __restrict__ Hm,
          const unsigned char* __restrict__ Wbf, float* __restrict__ AGG)
{
    __shared__ __align__(1024) unsigned char SB[24576];
    int tid = threadIdx.x, w = tid >> 5, lane = tid & 31;
    unsigned sb = smem_u32(SB);
    {
        const unsigned char* g = Eg + (size_t)blockIdx.x * 16384;
        #pragma unroll
        for (int i = 0; i < 8; i++) cpa16(sb + tid * 16 + i * 2048, g + tid * 16 + i * 2048);
        #pragma unroll
        for (int i = 0; i < 4; i++)
            cpa16(sb + 16384u + tid * 16 + i * 2048, Wbf + tid * 16 + i * 2048);
    }
    asm volatile("cp.async.commit_group;\ncp.async.wait_group 0;" ::: "memory");
    __syncthreads();

    float acc[2][8][4];
    #pragma unroll
    for (int mt = 0; mt < 2; mt++) for (int t = 0; t < 8; t++)
        for (int c = 0; c < 4; c++) acc[mt][t][c] = 0.f;
    mma_core(sb, sb + 16384u, acc, w, lane);

    int i4 = lane >> 2, j = lane & 3;
    #pragma unroll
    for (int mt = 0; mt < 2; mt++) {
        #pragma unroll
        for (int rr = 0; rr < 2; rr++) {
            int eloc = w * 32 + mt * 16 + rr * 8 + i4;
            long eg = (long)blockIdx.x * TE + eloc;
            int s = src[eg], d = dst[eg];
            const float4* hm = (const float4*)(Hm + (long)s * HID + j * 16);
            float* ag = AGG + (long)d * HID + j * 16;
            #pragma unroll
            for (int c = 0; c < 4; c++) {
                float4 h = hm[c];
                float v0 = fmaxf(acc[mt][2*c  ][rr*2+0] + h.x, 0.f);
                float v1 = fmaxf(acc[mt][2*c  ][rr*2+1] + h.y, 0.f);
                float v2 = fmaxf(acc[mt][2*c+1][rr*2+0] + h.z, 0.f);
                float v3 = fmaxf(acc[mt][2*c+1][rr*2+1] + h.w, 0.f);
                asm volatile("red.global.add.v4.f32 [%0], {%1,%2,%3,%4};"
                    :: "l"(ag + c * 4), "f"(v0), "f"(v1), "f"(v2), "f"(v3) : "memory");
            }
        }
    }
}

// ---------- h' = relu([h,agg]@Wu + bu) + h  (two-phase, 6-pass mma) ----------
__global__ void __launch_bounds__(128) k_update(
    const unsigned char* __restrict__ Hbf, const float* __restrict__ AGG,
    const float* __restrict__ Hin, const unsigned char* __restrict__ Wu2,
    const float* __restrict__ bu, float* __restrict__ Hout,
    unsigned char* __restrict__ Hbfout)
{
    __shared__ __align__(1024) unsigned char SB[49152]; // Ahi@0 Alo@16384 Whi@32768 Wlo@40960
    int tid = threadIdx.x, w = tid >> 5, lane = tid & 31;
    unsigned sb = smem_u32(SB);
    long r0 = (long)blockIdx.x * 128;
    {
        const unsigned char* g = Hbf + (size_t)blockIdx.x * 32768;
        #pragma unroll
        for (int i = 0; i < 16; i++) cpa16(sb + tid * 16 + i * 2048, g + tid * 16 + i * 2048);
        #pragma unroll
        for (int i = 0; i < 8; i++)
            cpa16(sb + 32768u + tid * 16 + i * 2048, Wu2 + tid * 16 + i * 2048);
    }
    asm volatile("cp.async.commit_group;\ncp.async.wait_group 0;" ::: "memory");
    __syncthreads();

    float acc[2][8][4];
    #pragma unroll
    for (int mt = 0; mt < 2; mt++) for (int t = 0; t < 8; t++)
        for (int c = 0; c < 4; c++) acc[mt][t][c] = 0.f;
    mma_core(sb,          sb + 32768u, acc, w, lane);
    mma_core(sb,          sb + 40960u, acc, w, lane);
    mma_core(sb + 16384u, sb + 32768u, acc, w, lane);
    __syncthreads();

    // phase 2: AGG fp32 -> hi/lo tiles over A region; Wu_bot hi/lo over W region
    {
        int jt = tid & 15, et = tid >> 4;
        int j0 = jt * 4;
        #pragma unroll
        for (int rr = 0; rr < 16; rr++) {
            int r = et * 16 + rr;
            long gr = r0 + r;
            float4 a = (gr < NNODES) ? *(const float4*)(AGG + gr * HID + j0)
                                     : make_float4(0.f, 0.f, 0.f, 0.f);
            unsigned sw = sw128((unsigned)r * 128u + (unsigned)j0 * 2u);
            st_hilo(sb, sb + 16384u, sw, a.x, a.y, a.z, a.w);
        }
        #pragma unroll
        for (int i = 0; i < 8; i++)
            cpa16(sb + 32768u + tid * 16 + i * 2048, Wu2 + 16384 + tid * 16 + i * 2048);
    }
    asm volatile("cp.async.commit_group;\ncp.async.wait_group 0;" ::: "memory");
    __syncthreads();
    mma_core(sb,          sb + 32768u, acc, w, lane);
    mma_core(sb,          sb + 40960u, acc, w, lane);
    mma_core(sb + 16384u, sb + 32768u, acc, w, lane);
    __syncthreads();

    int i4 = lane >> 2, j = lane & 3;
    #pragma unroll
    for (int mt = 0; mt < 2; mt++) {
        #pragma unroll
        for (int rr = 0; rr < 2; rr++) {
            int row = w * 32 + mt * 16 + rr * 8 + i4;
            long gr = r0 + row;
            bool valid = gr < NNODES;
            #pragma unroll
            for (int c = 0; c < 4; c++) {
                float4 bb = *(const float4*)(bu + j * 16 + c * 4);
                float4 h = valid ? *(const float4*)(Hin + gr * HID + j * 16 + c * 4)
                                 : make_float4(0.f, 0.f, 0.f, 0.f);
                float v0 = fmaxf(acc[mt][2*c  ][rr*2+0] + bb.x, 0.f) + h.x;
                float v1 = fmaxf(acc[mt][2*c  ][rr*2+1] + bb.y, 0.f) + h.y;
                float v2 = fmaxf(acc[mt][2*c+1][rr*2+0] + bb.z, 0.f) + h.z;
                float v3 = fmaxf(acc[mt][2*c+1][rr*2+1] + bb.w, 0.f) + h.w;
                if (!valid) { v0 = v1 = v2 = v3 = 0.f; }
                else *(float4*)(Hout + gr * HID + j * 16 + c * 4) = make_float4(v0,v1,v2,v3);
                unsigned sw = sw128((unsigned)row * 128u + (unsigned)(j * 16 + c * 4) * 2u);
                st_hilo(sb, sb + 16384u, sw, v0, v1, v2, v3);
            }
        }
    }
    __syncthreads();
    uint4* dst4 = (uint4*)(Hbfout + (size_t)blockIdx.x * 32768);
    #pragma unroll
    for (int i = 0; i < 16; i++) {
        uint4 v;
        asm volatile("ld.shared.v4.b32 {%0,%1,%2,%3},[%4];"
                     : "=r"(v.x), "=r"(v.y), "=r"(v.z), "=r"(v.w)
                     : "r"(sb + tid * 16 + i * 2048));
        dst4[tid + i * 128] = v;
    }
}

// ---------- A = h @ Ws1_top ; B = h @ Ws1_bot (two-phase W reload) ----------
__global__ void __launch_bounds__(128) k_ab(
    const unsigned char* __restrict__ Hbf, const unsigned char* __restrict__ Wt2,
    float* __restrict__ A, float* __restrict__ B)
{
    __shared__ __align__(1024) unsigned char SB[49152];
    int tid = threadIdx.x, w = tid >> 5, lane = tid & 31;
    unsigned sb = smem_u32(SB);
    const unsigned char* g = Hbf + (size_t)blockIdx.x * 32768;
    #pragma unroll
    for (int i = 0; i < 16; i++) cpa16(sb + tid * 16 + i * 2048, g + tid * 16 + i * 2048);
    #pragma unroll
    for (int i = 0; i < 8; i++)
        cpa16(sb + 32768u + tid * 16 + i * 2048, Wt2 + tid * 16 + i * 2048);
    asm volatile("cp.async.commit_group;\ncp.async.wait_group 0;" ::: "memory");
    __syncthreads();

    long r0 = (long)blockIdx.x * 128;
    int i4 = lane >> 2, j = lane & 3;
    float* outs[2] = {A, B};
    #pragma unroll
    for (int pass = 0; pass < 2; pass++) {
        float acc[2][8][4];
        #pragma unroll
        for (int mt = 0; mt < 2; mt++) for (int t = 0; t < 8; t++)
            for (int c = 0; c < 4; c++) acc[mt][t][c] = 0.f;
        mma_core(sb,          sb + 32768u, acc, w, lane);
        mma_core(sb,          sb + 40960u, acc, w, lane);
        mma_core(sb + 16384u, sb + 32768u, acc, w, lane);
        float* O = outs[pass];
        #pragma unroll
        for (int mt = 0; mt < 2; mt++) {
            #pragma unroll
            for (int rr = 0; rr < 2; rr++) {
                long gr = r0 + w * 32 + mt * 16 + rr * 8 + i4;
                if (gr < NNODES) {
                    float* o = O + gr * HID + j * 16;
                    #pragma unroll
                    for (int c = 0; c < 4; c++)
                        *(float4*)(o + c * 4) = make_float4(
                            acc[mt][2*c][rr*2+0], acc[mt][2*c][rr*2+1],
                            acc[mt][2*c+1][rr*2+0], acc[mt][2*c+1][rr*2+1]);
                }
            }
        }
        if (pass == 0) {
            __syncthreads();
            #pragma unroll
            for (int i = 0; i < 8; i++)
                cpa16(sb + 32768u + tid * 16 + i * 2048, Wt2 + 16384 + tid * 16 + i * 2048);
            asm volatile("cp.async.commit_group;\ncp.async.wait_group 0;" ::: "memory");
            __syncthreads();
        }
    }
}

// ---------- per-OD scores (also zeroes g_GE from block 0) ----------
__global__ __launch_bounds__(256) void k_scores(
    const float* __restrict__ A, const float* __restrict__ B,
    const int* __restrict__ ods, const int* __restrict__ odd,
    const float* __restrict__ bs1, const float* __restrict__ Ws2,
    const float* __restrict__ bs2, float* __restrict__ out)
{
    if (blockIdx.x == 0 && threadIdx.x < HID) g_GE[threadIdx.x] = 0.f;
    int warp = threadIdx.x >> 5, lane = threadIdx.x & 31;
    int p = blockIdx.x * 8 + warp;
    int s = ods[p], d = odd[p];
    const float* Ar = A + (long)s * HID;
    const float* Br = B + (long)d * HID;
    int j1 = lane, j2 = lane + 32;
    float t1 = fmaxf(Ar[j1] + Br[j1] + bs1[j1], 0.f);
    float t2 = fmaxf(Ar[j2] + Br[j2] + bs1[j2], 0.f);
    float v = t1 * Ws2[j1] + t2 * Ws2[j2];
    #pragma unroll
    for (int o = 16; o > 0; o >>= 1) v += __shfl_down_sync(0xffffffffu, v, o);
    if (lane == 0) out[p] = v + bs2[0];
}

// ---------- graph embed sum ----------
__global__ __launch_bounds__(256) void k_gesum(const float* __restrict__ H)
{
    __shared__ float part[4][HID];
    int tid = threadIdx.x;
    int j = tid & 63, g = tid >> 6;
    long base = (long)blockIdx.x * 256 + g;
    float acc = 0.f;
    #pragma unroll 4
    for (int i = 0; i < 64; i++) {
        long r = base + (long)i * 4;
        if (r < NNODES) acc += H[r * HID + j];
    }
    part[g][j] = acc;
    __syncthreads();
    if (g == 0) {
        float s = part[0][j] + part[1][j] + part[2][j] + part[3][j];
        atomicAdd(&g_GE[j], s);
    }
}

// ---------- dynamic-K head ----------
__global__ void k_khead(
    const float* __restrict__ TS,
    const float* __restrict__ Wk1, const float* __restrict__ bk1,
    const float* __restrict__ Wk2, const float* __restrict__ bk2,
    const float* __restrict__ Wk3, const float* __restrict__ bk3,
    float* __restrict__ out)
{
    __shared__ float x[68];
    __shared__ float h1[32];
    __shared__ float h2[16];
    int lane = threadIdx.x;
    x[lane]      = g_GE[lane] * (1.0f / NNODES);
    x[lane + 32] = g_GE[lane + 32] * (1.0f / NNODES);
    if (lane < 4) x[64 + lane] = TS[lane];
    __syncwarp();
    float a = bk1[lane];
    #pragma unroll 4
    for (int k = 0; k < 68; k++) a += x[k] * Wk1[k * 32 + lane];
    h1[lane] = fmaxf(a, 0.f);
    __syncwarp();
    if (lane < 16) {
        float b = bk2[lane];
        #pragma unroll
        for (int k = 0; k < 32; k++) b += h1[k] * Wk2[k * 16 + lane];
        h2[lane] = fmaxf(b, 0.f);
    }
    __syncwarp();
    if (lane == 0) {
        float raw = bk3[0];
        #pragma unroll
        for (int k = 0; k < 16; k++) raw += h2[k] * Wk3[k];
        float sig = 1.0f / (1.0f + expf(-raw));
        out[NOD] = KMIN + sig * (KMAX - KMIN);
    }
}

// ---------- launcher ----------
extern "C" void kernel_launch(void* const* d_in, const int* in_sizes, int n_in,
                              void* d_out, int out_size)
{
    const float* NF  = (const float*)d_in[0];
    const int*   EI  = (const int*)  d_in[1];
    const float* EF  = (const float*)d_in[2];
    const int*   OD  = (const int*)  d_in[3];
    const float* TS  = (const float*)d_in[4];
    const float* Wn  = (const float*)d_in[5];
    const float* bn  = (const float*)d_in[6];
    const float* We  = (const float*)d_in[7];
    const float* be  = (const float*)d_in[8];
    const float* Wm  = (const float*)d_in[9];
    const float* bm  = (const float*)d_in[10];
    const float* Wu  = (const float*)d_in[11];
    const float* bu  = (const float*)d_in[12];
    const float* Ws1 = (const float*)d_in[13];
    const float* bs1 = (const float*)d_in[14];
    const float* Ws2 = (const float*)d_in[15];
    const float* bs2 = (const float*)d_in[16];
    const float* Wk1 = (const float*)d_in[17];
    const float* bk1 = (const float*)d_in[18];
    const float* Wk2 = (const float*)d_in[19];
    const float* bk2 = (const float*)d_in[20];
    const float* Wk3 = (const float*)d_in[21];
    const float* bk3 = (const float*)d_in[22];
    float* out = (float*)d_out;

    unsigned char *E, *Hbf, *Wt;
    float *H0, *H1, *Hm, *AG;
    cudaGetSymbolAddress((void**)&E,   g_Ebf);
    cudaGetSymbolAddress((void**)&Hbf, g_Hbf);
    cudaGetSymbolAddress((void**)&Wt,  g_Wt);
    cudaGetSymbolAddress((void**)&H0,  g_H0);
    cudaGetSymbolAddress((void**)&H1,  g_H1);
    cudaGetSymbolAddress((void**)&Hm,  g_Hm);
    cudaGetSymbolAddress((void**)&AG,  g_AG);

    const int* src = EI;
    const int* dst = EI + NEDGES;
    const int* ods = OD;
    const int* odd = OD + NOD;

    k_node_proj<<<NTILE_N, 256>>>(NF, Wn, bn, H0, Hbf);
    k_edge_proj<<<NTILES, 256>>>(EF, We, be, E);
    k_wconv<<<14, 256>>>(Wm, Wu, Ws1, Wt);

    float* Hcur = H0;
    float* Hnext = H1;
    for (int l = 0; l < NLAYERS; l++) {
        k_hm<<<NTILE_N, 128>>>(Hbf, Wt + (size_t)(2 * l) * 8192,
                               bm + (size_t)l * HID, Hm, AG);
        k_edge_mp<<<NTILES, 128>>>(E, src, dst, Hm, Wt + (size_t)(2 * (3 + l)) * 8192, AG);
        k_update<<<NTILE_N, 128>>>(Hbf, AG, Hcur, Wt + (size_t)(2 * (6 + 2 * l)) * 8192,
                                   bu + (size_t)l * HID, Hnext, Hbf);
        float* t = Hcur; Hcur = Hnext; Hnext = t;
    }

    k_ab<<<NTILE_N, 128>>>(Hbf, Wt + (size_t)(2 * 12) * 8192, Hm, AG);
    k_scores<<<NOD / 8, 256>>>(Hm, AG, ods, odd, bs1, Ws2, bs2, out);

    k_gesum<<<(NNODES + 255) / 256, 256>>>(Hcur);
    k_khead<<<1, 32>>>(TS, Wk1, bk1, Wk2, bk2, Wk3, bk3, out);
}

// round 13
// speedup vs baseline: 2.6813x; 1.0928x over previous
#include <cuda_runtime.h>
#include <cuda_bf16.h>
#include <math.h>

#define NNODES 50000
#define NOD    10000
#define NEDGES 1200000
#define DNODE  16
#define DEDGE  8
#define HID    64
#define NLAYERS 3
#define TE     128
#define NTILES (NEDGES / TE)
#define NTILE_N 391
#define KMIN   1.0f
#define KMAX   50.0f

// ---------- scratch ----------
__device__ unsigned char g_Ebf[(size_t)NEDGES * HID * 2];     // SW128 edge tiles (bf16)
__device__ unsigned char g_Hbf[(size_t)NTILE_N * 32768];      // node tiles: hi(16K)+lo(16K)
__device__ unsigned char g_Wt [(size_t)28 * 8192];            // W tiles hi/lo
__device__ float g_H0[(size_t)NNODES * HID];
__device__ float g_H1[(size_t)NNODES * HID];
__device__ float g_Hm[(size_t)NNODES * HID];                  // bf16 Hm aliased here; fp32 A later
__device__ float g_AG[(size_t)NNODES * HID];
__device__ float g_GE[HID];

// ---------- packed f32x2 helpers ----------
__device__ __forceinline__ unsigned long long pack2(float x, float y) {
    unsigned long long r; asm("mov.b64 %0,{%1,%2};" : "=l"(r) : "f"(x), "f"(y)); return r;
}
__device__ __forceinline__ unsigned long long dup2(float x) {
    unsigned long long r; asm("mov.b64 %0,{%1,%1};" : "=l"(r) : "f"(x)); return r;
}
__device__ __forceinline__ float2 unpack2(unsigned long long v) {
    float2 f; asm("mov.b64 {%0,%1},%2;" : "=f"(f.x), "=f"(f.y) : "l"(v)); return f;
}
__device__ __forceinline__ void fma2(unsigned long long& a,
                                     unsigned long long x, unsigned long long y) {
    asm("fma.rn.f32x2 %0,%1,%2,%0;" : "+l"(a) : "l"(x), "l"(y));
}

// ---------- async / mma helpers ----------
__device__ __forceinline__ unsigned smem_u32(const void* p) {
    unsigned a;
    asm("{.reg .u64 t; cvta.to.shared.u64 t, %1; cvt.u32.u64 %0, t;}" : "=r"(a) : "l"(p));
    return a;
}
__device__ __forceinline__ void cpa16(unsigned s, const void* g) {
    asm volatile("cp.async.cg.shared.global [%0], [%1], 16;" :: "r"(s), "l"(g));
}
__device__ __forceinline__ void ldm4(unsigned& r0, unsigned& r1, unsigned& r2, unsigned& r3,
                                     unsigned addr) {
    asm volatile("ldmatrix.sync.aligned.m8n8.x4.shared.b16 {%0,%1,%2,%3},[%4];"
                 : "=r"(r0), "=r"(r1), "=r"(r2), "=r"(r3) : "r"(addr));
}
__device__ __forceinline__ void mma16816(float* c, unsigned a0, unsigned a1,
                                         unsigned a2, unsigned a3, unsigned b0, unsigned b1) {
    asm volatile("mma.sync.aligned.m16n8k16.row.col.f32.bf16.bf16.f32 "
                 "{%0,%1,%2,%3},{%4,%5,%6,%7},{%8,%9},{%0,%1,%2,%3};"
                 : "+f"(c[0]), "+f"(c[1]), "+f"(c[2]), "+f"(c[3])
                 : "r"(a0), "r"(a1), "r"(a2), "r"(a3), "r"(b0), "r"(b1));
}
__device__ __forceinline__ unsigned sw128(unsigned off) {
    return off ^ ((off >> 3) & 0x70u);
}
__device__ __forceinline__ void st_hilo(unsigned sb_hi, unsigned sb_lo, unsigned sw,
                                        float v0, float v1, float v2, float v3) {
    __nv_bfloat16 h0 = __float2bfloat16(v0), h1 = __float2bfloat16(v1);
    __nv_bfloat16 h2 = __float2bfloat16(v2), h3 = __float2bfloat16(v3);
    __nv_bfloat16 l0 = __float2bfloat16(v0 - __bfloat162float(h0));
    __nv_bfloat16 l1 = __float2bfloat16(v1 - __bfloat162float(h1));
    __nv_bfloat16 l2 = __float2bfloat16(v2 - __bfloat162float(h2));
    __nv_bfloat16 l3 = __float2bfloat16(v3 - __bfloat162float(h3));
    unsigned hp0 = ((unsigned)*(unsigned short*)&h1 << 16) | *(unsigned short*)&h0;
    unsigned hp1 = ((unsigned)*(unsigned short*)&h3 << 16) | *(unsigned short*)&h2;
    unsigned lp0 = ((unsigned)*(unsigned short*)&l1 << 16) | *(unsigned short*)&l0;
    unsigned lp1 = ((unsigned)*(unsigned short*)&l3 << 16) | *(unsigned short*)&l2;
    asm volatile("st.shared.v2.b32 [%0],{%1,%2};" :: "r"(sb_hi + sw), "r"(hp0), "r"(hp1) : "memory");
    asm volatile("st.shared.v2.b32 [%0],{%1,%2};" :: "r"(sb_lo + sw), "r"(lp0), "r"(lp1) : "memory");
}
// store 4 floats as 4 bf16 (8 bytes) to global
__device__ __forceinline__ void st_bf4(__nv_bfloat16* p, float v0, float v1, float v2, float v3) {
    __nv_bfloat162 p0 = __floats2bfloat162_rn(v0, v1);
    __nv_bfloat162 p1 = __floats2bfloat162_rn(v2, v3);
    unsigned long long pk = ((unsigned long long)*(unsigned*)&p1 << 32) | *(unsigned*)&p0;
    *(unsigned long long*)p = pk;
}

// shared 128x64x64 mma core
__device__ __forceinline__ void mma_core(unsigned abase, unsigned bbase,
                                         float acc[2][8][4], int w, int lane)
{
    int q = lane >> 3, rloc = lane & 7;
    #pragma unroll
    for (int kk = 0; kk < 4; kk++) {
        unsigned bf[16];
        #pragma unroll
        for (int tp = 0; tp < 4; tp++) {
            unsigned row = (unsigned)((2 * tp + (q >> 1)) * 8 + rloc);
            unsigned colb = (unsigned)(kk * 32 + (q & 1) * 16);
            ldm4(bf[4*tp+0], bf[4*tp+1], bf[4*tp+2], bf[4*tp+3],
                 bbase + sw128(row * 128u + colb));
        }
        #pragma unroll
        for (int mt = 0; mt < 2; mt++) {
            unsigned a0, a1, a2, a3;
            unsigned row = (unsigned)(w * 32 + mt * 16 + (q & 1) * 8 + rloc);
            unsigned colb = (unsigned)(kk * 32 + (q >> 1) * 16);
            ldm4(a0, a1, a2, a3, abase + sw128(row * 128u + colb));
            #pragma unroll
            for (int t = 0; t < 8; t++)
                mma16816(acc[mt][t], a0, a1, a2, a3, bf[2*t], bf[2*t+1]);
        }
    }
}

// ---------- h0 = relu(NF @ Wn + bn) -> H fp32 + Hbf hi/lo tile ----------
__global__ __launch_bounds__(256) void k_node_proj(
    const float* __restrict__ NF, const float* __restrict__ Wn,
    const float* __restrict__ bn, float* __restrict__ H, unsigned char* __restrict__ Hbf)
{
    __shared__ float Ws[DNODE * HID];
    __shared__ float efs[128 * DNODE];
    __shared__ __align__(16) unsigned char Es[32768];
    int tid = threadIdx.x;
    long r0 = (long)blockIdx.x * 128;
    ((float4*)Ws)[tid] = ((const float4*)Wn)[tid];
    #pragma unroll
    for (int i = 0; i < 2; i++) {
        int idx = tid + i * 256;
        long gr = r0 + (idx >> 2);
        ((float4*)efs)[idx] = (gr < NNODES) ? ((const float4*)NF)[gr * 4 + (idx & 3)]
                                            : make_float4(0.f, 0.f, 0.f, 0.f);
    }
    __syncthreads();
    unsigned es = smem_u32(Es);
    int jt = tid & 15, et = tid >> 4;
    int j0 = jt * 4;
    float4 b = *(const float4*)(bn + j0);
    #pragma unroll
    for (int ee = 0; ee < 8; ee++) {
        int e = et * 8 + ee;
        long gr = r0 + e;
        unsigned long long a0 = pack2(b.x, b.y), a1 = pack2(b.z, b.w);
        const float* x = efs + e * DNODE;
        #pragma unroll
        for (int k = 0; k < DNODE; k++) {
            unsigned long long ap = dup2(x[k]);
            const unsigned long long* w = (const unsigned long long*)(Ws + k * HID + j0);
            fma2(a0, ap, w[0]); fma2(a1, ap, w[1]);
        }
        float2 v0 = unpack2(a0), v1 = unpack2(a1);
        float o0 = fmaxf(v0.x,0.f), o1 = fmaxf(v0.y,0.f);
        float o2 = fmaxf(v1.x,0.f), o3 = fmaxf(v1.y,0.f);
        if (gr >= NNODES) { o0 = o1 = o2 = o3 = 0.f; }
        else *(float4*)(H + gr * HID + j0) = make_float4(o0, o1, o2, o3);
        unsigned sw = sw128((unsigned)e * 128u + (unsigned)j0 * 2u);
        st_hilo(es, es + 16384u, sw, o0, o1, o2, o3);
    }
    __syncthreads();
    uint4* dst4 = (uint4*)(Hbf + (size_t)blockIdx.x * 32768);
    const uint4* src4 = (const uint4*)Es;
    #pragma unroll
    for (int i = 0; i < 8; i++) dst4[tid + i * 256] = src4[tid + i * 256];
}

// ---------- E tile = relu(EF @ We + be), bf16 single, SW128 ----------
__global__ __launch_bounds__(256) void k_edge_proj(
    const float* __restrict__ EF, const float* __restrict__ We,
    const float* __restrict__ be, unsigned char* __restrict__ E)
{
    __shared__ float Ws[DEDGE * HID];
    __shared__ float efs[TE * DEDGE];
    __shared__ __align__(16) unsigned char Es[16384];
    int tid = threadIdx.x;
    long e0g = (long)blockIdx.x * TE;
    if (tid < 128) ((float4*)Ws)[tid] = ((const float4*)We)[tid];
    ((float4*)efs)[tid] = ((const float4*)(EF + e0g * DEDGE))[tid];
    __syncthreads();
    int jt = tid & 15, et = tid >> 4;
    int j0 = jt * 4;
    float4 b = *(const float4*)(be + j0);
    #pragma unroll
    for (int ee = 0; ee < 8; ee++) {
        int e = et * 8 + ee;
        unsigned long long a0 = pack2(b.x, b.y), a1 = pack2(b.z, b.w);
        const float* x = efs + e * DEDGE;
        #pragma unroll
        for (int k = 0; k < DEDGE; k++) {
            unsigned long long ap = dup2(x[k]);
            const unsigned long long* w = (const unsigned long long*)(Ws + k * HID + j0);
            fma2(a0, ap, w[0]); fma2(a1, ap, w[1]);
        }
        float2 v0 = unpack2(a0), v1 = unpack2(a1);
        __nv_bfloat162 p0 = __floats2bfloat162_rn(fmaxf(v0.x,0.f), fmaxf(v0.y,0.f));
        __nv_bfloat162 p1 = __floats2bfloat162_rn(fmaxf(v1.x,0.f), fmaxf(v1.y,0.f));
        unsigned sw = sw128((unsigned)e * 128u + (unsigned)j0 * 2u);
        *(unsigned*)(Es + sw)     = *(unsigned*)&p0;
        *(unsigned*)(Es + sw + 4) = *(unsigned*)&p1;
    }
    __syncthreads();
    uint4* dst4 = (uint4*)(E + (size_t)blockIdx.x * 16384);
    const uint4* src4 = (const uint4*)Es;
    #pragma unroll
    for (int i = 0; i < 4; i++) dst4[tid + i * 256] = src4[tid + i * 256];
}

// ---------- all W -> col-permuted SW128 hi/lo tiles ----------
__global__ void k_wconv(const float* __restrict__ Wm, const float* __restrict__ Wu,
                        const float* __restrict__ Ws1, unsigned char* __restrict__ Wt)
{
    int b = blockIdx.x;
    const float* src;
    if (b < 3)       src = Wm + (size_t)b * 2 * HID * HID;
    else if (b < 6)  src = Wm + (size_t)(b - 3) * 2 * HID * HID + (size_t)HID * HID;
    else if (b < 12) src = Wu + (size_t)((b - 6) >> 1) * 2 * HID * HID
                              + (size_t)((b - 6) & 1) * HID * HID;
    else             src = Ws1 + (size_t)(b - 12) * HID * HID;
    unsigned char* ohi = Wt + (size_t)(2 * b) * 8192;
    unsigned char* olo = ohi + 8192;
    for (int i = threadIdx.x; i < HID * HID; i += blockDim.x) {
        int p = i >> 6, k = i & 63;
        int L = ((p & 7) >> 1) * 16 + (p >> 3) * 2 + (p & 1);
        float v = src[k * HID + L];
        __nv_bfloat16 hi = __float2bfloat16(v);
        __nv_bfloat16 lo = __float2bfloat16(v - __bfloat162float(hi));
        unsigned sw = sw128((unsigned)p * 128u + (unsigned)k * 2u);
        *(__nv_bfloat16*)(ohi + sw) = hi;
        *(__nv_bfloat16*)(olo + sw) = lo;
    }
}

// ---------- Hm = h @ Wm_top + bm (3-pass mma) -> bf16; AGG = 0 ----------
__global__ void __launch_bounds__(128) k_hm(
    const unsigned char* __restrict__ Hbf, const unsigned char* __restrict__ Wt,
    const float* __restrict__ bm, __nv_bfloat16* __restrict__ Hmb, float* __restrict__ AGG)
{
    __shared__ __align__(1024) unsigned char SB[49152];
    int tid = threadIdx.x, w = tid >> 5, lane = tid & 31;
    unsigned sb = smem_u32(SB);
    const unsigned char* g = Hbf + (size_t)blockIdx.x * 32768;
    #pragma unroll
    for (int i = 0; i < 16; i++) cpa16(sb + tid * 16 + i * 2048, g + tid * 16 + i * 2048);
    #pragma unroll
    for (int i = 0; i < 8; i++)
        cpa16(sb + 32768u + tid * 16 + i * 2048, Wt + tid * 16 + i * 2048);
    asm volatile("cp.async.commit_group;\ncp.async.wait_group 0;" ::: "memory");
    __syncthreads();

    float acc[2][8][4];
    #pragma unroll
    for (int mt = 0; mt < 2; mt++) for (int t = 0; t < 8; t++)
        for (int c = 0; c < 4; c++) acc[mt][t][c] = 0.f;
    mma_core(sb,          sb + 32768u, acc, w, lane);
    mma_core(sb,          sb + 40960u, acc, w, lane);
    mma_core(sb + 16384u, sb + 32768u, acc, w, lane);

    long r0 = (long)blockIdx.x * 128;
    int i4 = lane >> 2, j = lane & 3;
    #pragma unroll
    for (int mt = 0; mt < 2; mt++) {
        #pragma unroll
        for (int rr = 0; rr < 2; rr++) {
            long gr = r0 + w * 32 + mt * 16 + rr * 8 + i4;
            if (gr < NNODES) {
                float* ag = AGG + gr * HID + j * 16;
                #pragma unroll
                for (int c = 0; c < 4; c++) {
                    float4 bb = *(const float4*)(bm + j * 16 + c * 4);
                    st_bf4(Hmb + gr * HID + j * 16 + c * 4,
                           acc[mt][2*c][rr*2+0] + bb.x, acc[mt][2*c][rr*2+1] + bb.y,
                           acc[mt][2*c+1][rr*2+0] + bb.z, acc[mt][2*c+1][rr*2+1] + bb.w);
                    *(float4*)(ag + c * 4) = make_float4(0.f, 0.f, 0.f, 0.f);
                }
            }
        }
    }
}

// ---------- per-tile mma message GEMM + fused gather/scatter (bf16 Hm) ----------
__global__ void __launch_bounds__(128)
k_edge_mp(const unsigned char* __restrict__ Eg, const int* __restrict__ src,
          const int* __restrict__ dst, const __nv_bfloat16* __restrict__ Hmb,
          const unsigned char* __restrict__ Wbf, float* __restrict__ AGG)
{
    __shared__ __align__(1024) unsigned char SB[24576];
    int tid = threadIdx.x, w = tid >> 5, lane = tid & 31;
    unsigned sb = smem_u32(SB);
    {
        const unsigned char* g = Eg + (size_t)blockIdx.x * 16384;
        #pragma unroll
        for (int i = 0; i < 8; i++) cpa16(sb + tid * 16 + i * 2048, g + tid * 16 + i * 2048);
        #pragma unroll
        for (int i = 0; i < 4; i++)
            cpa16(sb + 16384u + tid * 16 + i * 2048, Wbf + tid * 16 + i * 2048);
    }
    asm volatile("cp.async.commit_group;\ncp.async.wait_group 0;" ::: "memory");
    __syncthreads();

    float acc[2][8][4];
    #pragma unroll
    for (int mt = 0; mt < 2; mt++) for (int t = 0; t < 8; t++)
        for (int c = 0; c < 4; c++) acc[mt][t][c] = 0.f;
    mma_core(sb, sb + 16384u, acc, w, lane);

    int i4 = lane >> 2, j = lane & 3;
    #pragma unroll
    for (int mt = 0; mt < 2; mt++) {
        #pragma unroll
        for (int rr = 0; rr < 2; rr++) {
            int eloc = w * 32 + mt * 16 + rr * 8 + i4;
            long eg = (long)blockIdx.x * TE + eloc;
            int s = src[eg], d = dst[eg];
            const uint4* hm4 = (const uint4*)((const unsigned char*)Hmb
                                              + (size_t)s * 128 + (size_t)j * 32);
            uint4 ha = hm4[0], hb = hm4[1];
            float hf[16];
            {
                const __nv_bfloat162* bp = (const __nv_bfloat162*)&ha;
                #pragma unroll
                for (int q = 0; q < 4; q++) {
                    float2 f = __bfloat1622float2(bp[q]);
                    hf[2*q] = f.x; hf[2*q+1] = f.y;
                }
                bp = (const __nv_bfloat162*)&hb;
                #pragma unroll
                for (int q = 0; q < 4; q++) {
                    float2 f = __bfloat1622float2(bp[q]);
                    hf[8+2*q] = f.x; hf[8+2*q+1] = f.y;
                }
            }
            float* ag = AGG + (long)d * HID + j * 16;
            #pragma unroll
            for (int c = 0; c < 4; c++) {
                float v0 = fmaxf(acc[mt][2*c  ][rr*2+0] + hf[4*c+0], 0.f);
                float v1 = fmaxf(acc[mt][2*c  ][rr*2+1] + hf[4*c+1], 0.f);
                float v2 = fmaxf(acc[mt][2*c+1][rr*2+0] + hf[4*c+2], 0.f);
                float v3 = fmaxf(acc[mt][2*c+1][rr*2+1] + hf[4*c+3], 0.f);
                asm volatile("red.global.add.v4.f32 [%0], {%1,%2,%3,%4};"
                    :: "l"(ag + c * 4), "f"(v0), "f"(v1), "f"(v2), "f"(v3) : "memory");
            }
        }
    }
}

// ---------- h' = relu([h,agg]@Wu + bu) + h ; optional fused next-layer Hm ----------
__global__ void __launch_bounds__(128) k_update(
    const unsigned char* __restrict__ Hbf, float* __restrict__ AGG,
    const float* __restrict__ Hin, const unsigned char* __restrict__ Wu2,
    const float* __restrict__ bu, float* __restrict__ Hout,
    unsigned char* __restrict__ Hbfout,
    const unsigned char* __restrict__ Wmn, const float* __restrict__ bmn,
    __nv_bfloat16* __restrict__ Hmb, int do_hm)
{
    __shared__ __align__(1024) unsigned char SB[49152]; // Ahi@0 Alo@16384 W hi/lo@32768
    int tid = threadIdx.x, w = tid >> 5, lane = tid & 31;
    unsigned sb = smem_u32(SB);
    long r0 = (long)blockIdx.x * 128;
    {
        const unsigned char* g = Hbf + (size_t)blockIdx.x * 32768;
        #pragma unroll
        for (int i = 0; i < 16; i++) cpa16(sb + tid * 16 + i * 2048, g + tid * 16 + i * 2048);
        #pragma unroll
        for (int i = 0; i < 8; i++)
            cpa16(sb + 32768u + tid * 16 + i * 2048, Wu2 + tid * 16 + i * 2048);
    }
    asm volatile("cp.async.commit_group;\ncp.async.wait_group 0;" ::: "memory");
    __syncthreads();

    float acc[2][8][4];
    #pragma unroll
    for (int mt = 0; mt < 2; mt++) for (int t = 0; t < 8; t++)
        for (int c = 0; c < 4; c++) acc[mt][t][c] = 0.f;
    mma_core(sb,          sb + 32768u, acc, w, lane);
    mma_core(sb,          sb + 40960u, acc, w, lane);
    mma_core(sb + 16384u, sb + 32768u, acc, w, lane);
    __syncthreads();

    // phase 2: AGG fp32 -> hi/lo over A region; Wu_bot hi/lo over W region
    {
        int jt = tid & 15, et = tid >> 4;
        int j0 = jt * 4;
        #pragma unroll
        for (int rr = 0; rr < 16; rr++) {
            int r = et * 16 + rr;
            long gr = r0 + r;
            float4 a = (gr < NNODES) ? *(const float4*)(AGG + gr * HID + j0)
                                     : make_float4(0.f, 0.f, 0.f, 0.f);
            unsigned sw = sw128((unsigned)r * 128u + (unsigned)j0 * 2u);
            st_hilo(sb, sb + 16384u, sw, a.x, a.y, a.z, a.w);
        }
        #pragma unroll
        for (int i = 0; i < 8; i++)
            cpa16(sb + 32768u + tid * 16 + i * 2048, Wu2 + 16384 + tid * 16 + i * 2048);
    }
    asm volatile("cp.async.commit_group;\ncp.async.wait_group 0;" ::: "memory");
    __syncthreads();
    mma_core(sb,          sb + 32768u, acc, w, lane);
    mma_core(sb,          sb + 40960u, acc, w, lane);
    mma_core(sb + 16384u, sb + 32768u, acc, w, lane);
    __syncthreads();

    // prefetch next-layer Wm_top hi/lo into W region (overlaps epilogue)
    if (do_hm) {
        #pragma unroll
        for (int i = 0; i < 8; i++)
            cpa16(sb + 32768u + tid * 16 + i * 2048, Wmn + tid * 16 + i * 2048);
        asm volatile("cp.async.commit_group;" ::: "memory");
    }

    int i4 = lane >> 2, j = lane & 3;
    #pragma unroll
    for (int mt = 0; mt < 2; mt++) {
        #pragma unroll
        for (int rr = 0; rr < 2; rr++) {
            int row = w * 32 + mt * 16 + rr * 8 + i4;
            long gr = r0 + row;
            bool valid = gr < NNODES;
            #pragma unroll
            for (int c = 0; c < 4; c++) {
                float4 bb = *(const float4*)(bu + j * 16 + c * 4);
                float4 h = valid ? *(const float4*)(Hin + gr * HID + j * 16 + c * 4)
                                 : make_float4(0.f, 0.f, 0.f, 0.f);
                float v0 = fmaxf(acc[mt][2*c  ][rr*2+0] + bb.x, 0.f) + h.x;
                float v1 = fmaxf(acc[mt][2*c  ][rr*2+1] + bb.y, 0.f) + h.y;
                float v2 = fmaxf(acc[mt][2*c+1][rr*2+0] + bb.z, 0.f) + h.z;
                float v3 = fmaxf(acc[mt][2*c+1][rr*2+1] + bb.w, 0.f) + h.w;
                if (!valid) { v0 = v1 = v2 = v3 = 0.f; }
                else *(float4*)(Hout + gr * HID + j * 16 + c * 4) = make_float4(v0,v1,v2,v3);
                unsigned sw = sw128((unsigned)row * 128u + (unsigned)(j * 16 + c * 4) * 2u);
                st_hilo(sb, sb + 16384u, sw, v0, v1, v2, v3);
            }
        }
    }
    __syncthreads();
    uint4* dst4 = (uint4*)(Hbfout + (size_t)blockIdx.x * 32768);
    #pragma unroll
    for (int i = 0; i < 16; i++) {
        uint4 v;
        asm volatile("ld.shared.v4.b32 {%0,%1,%2,%3},[%4];"
                     : "=r"(v.x), "=r"(v.y), "=r"(v.z), "=r"(v.w)
                     : "r"(sb + tid * 16 + i * 2048));
        dst4[tid + i * 128] = v;
    }

    // phase 3: next-layer Hm = h_new @ Wm_top + bm (A region holds new h hi/lo)
    if (do_hm) {
        asm volatile("cp.async.wait_group 0;" ::: "memory");
        __syncthreads();
        float ac2[2][8][4];
        #pragma unroll
        for (int mt = 0; mt < 2; mt++) for (int t = 0; t < 8; t++)
            for (int c = 0; c < 4; c++) ac2[mt][t][c] = 0.f;
        mma_core(sb,          sb + 32768u, ac2, w, lane);
        mma_core(sb,          sb + 40960u, ac2, w, lane);
        mma_core(sb + 16384u, sb + 32768u, ac2, w, lane);
        #pragma unroll
        for (int mt = 0; mt < 2; mt++) {
            #pragma unroll
            for (int rr = 0; rr < 2; rr++) {
                long gr = r0 + w * 32 + mt * 16 + rr * 8 + i4;
                if (gr < NNODES) {
                    float* ag = AGG + gr * HID + j * 16;
                    #pragma unroll
                    for (int c = 0; c < 4; c++) {
                        float4 bb = *(const float4*)(bmn + j * 16 + c * 4);
                        st_bf4(Hmb + gr * HID + j * 16 + c * 4,
                               ac2[mt][2*c][rr*2+0] + bb.x, ac2[mt][2*c][rr*2+1] + bb.y,
                               ac2[mt][2*c+1][rr*2+0] + bb.z, ac2[mt][2*c+1][rr*2+1] + bb.w);
                        *(float4*)(ag + c * 4) = make_float4(0.f, 0.f, 0.f, 0.f);
                    }
                }
            }
        }
    }
}

// ---------- A = h @ Ws1_top ; B = h @ Ws1_bot (two-phase W reload) ----------
__global__ void __launch_bounds__(128) k_ab(
    const unsigned char* __restrict__ Hbf, const unsigned char* __restrict__ Wt2,
    float* __restrict__ A, float* __restrict__ B)
{
    __shared__ __align__(1024) unsigned char SB[49152];
    int tid = threadIdx.x, w = tid >> 5, lane = tid & 31;
    unsigned sb = smem_u32(SB);
    const unsigned char* g = Hbf + (size_t)blockIdx.x * 32768;
    #pragma unroll
    for (int i = 0; i < 16; i++) cpa16(sb + tid * 16 + i * 2048, g + tid * 16 + i * 2048);
    #pragma unroll
    for (int i = 0; i < 8; i++)
        cpa16(sb + 32768u + tid * 16 + i * 2048, Wt2 + tid * 16 + i * 2048);
    asm volatile("cp.async.commit_group;\ncp.async.wait_group 0;" ::: "memory");
    __syncthreads();

    long r0 = (long)blockIdx.x * 128;
    int i4 = lane >> 2, j = lane & 3;
    float* outs[2] = {A, B};
    #pragma unroll
    for (int pass = 0; pass < 2; pass++) {
        float acc[2][8][4];
        #pragma unroll
        for (int mt = 0; mt < 2; mt++) for (int t = 0; t < 8; t++)
            for (int c = 0; c < 4; c++) acc[mt][t][c] = 0.f;
        mma_core(sb,          sb + 32768u, acc, w, lane);
        mma_core(sb,          sb + 40960u, acc, w, lane);
        mma_core(sb + 16384u, sb + 32768u, acc, w, lane);
        float* O = outs[pass];
        #pragma unroll
        for (int mt = 0; mt < 2; mt++) {
            #pragma unroll
            for (int rr = 0; rr < 2; rr++) {
                long gr = r0 + w * 32 + mt * 16 + rr * 8 + i4;
                if (gr < NNODES) {
                    float* o = O + gr * HID + j * 16;
                    #pragma unroll
                    for (int c = 0; c < 4; c++)
                        *(float4*)(o + c * 4) = make_float4(
                            acc[mt][2*c][rr*2+0], acc[mt][2*c][rr*2+1],
                            acc[mt][2*c+1][rr*2+0], acc[mt][2*c+1][rr*2+1]);
                }
            }
        }
        if (pass == 0) {
            __syncthreads();
            #pragma unroll
            for (int i = 0; i < 8; i++)
                cpa16(sb + 32768u + tid * 16 + i * 2048, Wt2 + 16384 + tid * 16 + i * 2048);
            asm volatile("cp.async.commit_group;\ncp.async.wait_group 0;" ::: "memory");
            __syncthreads();
        }
    }
}

// ---------- per-OD scores (also zeroes g_GE from block 0) ----------
__global__ __launch_bounds__(256) void k_scores(
    const float* __restrict__ A, const float* __restrict__ B,
    const int* __restrict__ ods, const int* __restrict__ odd,
    const float* __restrict__ bs1, const float* __restrict__ Ws2,
    const float* __restrict__ bs2, float* __restrict__ out)
{
    if (blockIdx.x == 0 && threadIdx.x < HID) g_GE[threadIdx.x] = 0.f;
    int warp = threadIdx.x >> 5, lane = threadIdx.x & 31;
    int p = blockIdx.x * 8 + warp;
    int s = ods[p], d = odd[p];
    const float* Ar = A + (long)s * HID;
    const float* Br = B + (long)d * HID;
    int j1 = lane, j2 = lane + 32;
    float t1 = fmaxf(Ar[j1] + Br[j1] + bs1[j1], 0.f);
    float t2 = fmaxf(Ar[j2] + Br[j2] + bs1[j2], 0.f);
    float v = t1 * Ws2[j1] + t2 * Ws2[j2];
    #pragma unroll
    for (int o = 16; o > 0; o >>= 1) v += __shfl_down_sync(0xffffffffu, v, o);
    if (lane == 0) out[p] = v + bs2[0];
}

// ---------- graph embed sum ----------
__global__ __launch_bounds__(256) void k_gesum(const float* __restrict__ H)
{
    __shared__ float part[4][HID];
    int tid = threadIdx.x;
    int j = tid & 63, g = tid >> 6;
    long base = (long)blockIdx.x * 256 + g;
    float acc = 0.f;
    #pragma unroll 4
    for (int i = 0; i < 64; i++) {
        long r = base + (long)i * 4;
        if (r < NNODES) acc += H[r * HID + j];
    }
    part[g][j] = acc;
    __syncthreads();
    if (g == 0) {
        float s = part[0][j] + part[1][j] + part[2][j] + part[3][j];
        atomicAdd(&g_GE[j], s);
    }
}

// ---------- dynamic-K head ----------
__global__ void k_khead(
    const float* __restrict__ TS,
    const float* __restrict__ Wk1, const float* __restrict__ bk1,
    const float* __restrict__ Wk2, const float* __restrict__ bk2,
    const float* __restrict__ Wk3, const float* __restrict__ bk3,
    float* __restrict__ out)
{
    __shared__ float x[68];
    __shared__ float h1[32];
    __shared__ float h2[16];
    int lane = threadIdx.x;
    x[lane]      = g_GE[lane] * (1.0f / NNODES);
    x[lane + 32] = g_GE[lane + 32] * (1.0f / NNODES);
    if (lane < 4) x[64 + lane] = TS[lane];
    __syncwarp();
    float a = bk1[lane];
    #pragma unroll 4
    for (int k = 0; k < 68; k++) a += x[k] * Wk1[k * 32 + lane];
    h1[lane] = fmaxf(a, 0.f);
    __syncwarp();
    if (lane < 16) {
        float b = bk2[lane];
        #pragma unroll
        for (int k = 0; k < 32; k++) b += h1[k] * Wk2[k * 16 + lane];
        h2[lane] = fmaxf(b, 0.f);
    }
    __syncwarp();
    if (lane == 0) {
        float raw = bk3[0];
        #pragma unroll
        for (int k = 0; k < 16; k++) raw += h2[k] * Wk3[k];
        float sig = 1.0f / (1.0f + expf(-raw));
        out[NOD] = KMIN + sig * (KMAX - KMIN);
    }
}

// ---------- launcher ----------
extern "C" void kernel_launch(void* const* d_in, const int* in_sizes, int n_in,
                              void* d_out, int out_size)
{
    const float* NF  = (const float*)d_in[0];
    const int*   EI  = (const int*)  d_in[1];
    const float* EF  = (const float*)d_in[2];
    const int*   OD  = (const int*)  d_in[3];
    const float* TS  = (const float*)d_in[4];
    const float* Wn  = (const float*)d_in[5];
    const float* bn  = (const float*)d_in[6];
    const float* We  = (const float*)d_in[7];
    const float* be  = (const float*)d_in[8];
    const float* Wm  = (const float*)d_in[9];
    const float* bm  = (const float*)d_in[10];
    const float* Wu  = (const float*)d_in[11];
    const float* bu  = (const float*)d_in[12];
    const float* Ws1 = (const float*)d_in[13];
    const float* bs1 = (const float*)d_in[14];
    const float* Ws2 = (const float*)d_in[15];
    const float* bs2 = (const float*)d_in[16];
    const float* Wk1 = (const float*)d_in[17];
    const float* bk1 = (const float*)d_in[18];
    const float* Wk2 = (const float*)d_in[19];
    const float* bk2 = (const float*)d_in[20];
    const float* Wk3 = (const float*)d_in[21];
    const float* bk3 = (const float*)d_in[22];
    float* out = (float*)d_out;

    unsigned char *E, *Hbf, *Wt;
    float *H0, *H1, *Hm, *AG;
    cudaGetSymbolAddress((void**)&E,   g_Ebf);
    cudaGetSymbolAddress((void**)&Hbf, g_Hbf);
    cudaGetSymbolAddress((void**)&Wt,  g_Wt);
    cudaGetSymbolAddress((void**)&H0,  g_H0);
    cudaGetSymbolAddress((void**)&H1,  g_H1);
    cudaGetSymbolAddress((void**)&Hm,  g_Hm);
    cudaGetSymbolAddress((void**)&AG,  g_AG);
    __nv_bfloat16* Hmb = (__nv_bfloat16*)Hm;

    const int* src = EI;
    const int* dst = EI + NEDGES;
    const int* ods = OD;
    const int* odd = OD + NOD;

    k_node_proj<<<NTILE_N, 256>>>(NF, Wn, bn, H0, Hbf);
    k_edge_proj<<<NTILES, 256>>>(EF, We, be, E);
    k_wconv<<<14, 256>>>(Wm, Wu, Ws1, Wt);

    k_hm<<<NTILE_N, 128>>>(Hbf, Wt, bm, Hmb, AG);   // layer 0 Wm_top = tile 0

    float* Hcur = H0;
    float* Hnext = H1;
    for (int l = 0; l < NLAYERS; l++) {
        k_edge_mp<<<NTILES, 128>>>(E, src, dst, Hmb, Wt + (size_t)(2 * (3 + l)) * 8192, AG);
        int do_hm = (l < NLAYERS - 1);
        k_update<<<NTILE_N, 128>>>(Hbf, AG, Hcur, Wt + (size_t)(2 * (6 + 2 * l)) * 8192,
                                   bu + (size_t)l * HID, Hnext, Hbf,
                                   Wt + (size_t)(2 * (l + 1)) * 8192,
                                   bm + (size_t)(l + 1 < NLAYERS ? l + 1 : 0) * HID,
                                   Hmb, do_hm);
        float* t = Hcur; Hcur = Hnext; Hnext = t;
    }

    k_ab<<<NTILE_N, 128>>>(Hbf, Wt + (size_t)(2 * 12) * 8192, Hm, AG);
    k_scores<<<NOD / 8, 256>>>(Hm, AG, ods, odd, bs1, Ws2, bs2, out);

    k_gesum<<<(NNODES + 255) / 256, 256>>>(Hcur);
    k_khead<<<1, 32>>>(TS, Wk1, bk1, Wk2, bk2, Wk3, bk3, out);
}